// round 2
// baseline (speedup 1.0000x reference)
#include <cuda_runtime.h>
#include <math.h>

#define B_ 8
#define T_ 1024
#define F_ 512
#define H_ 8
#define DK_ 64
#define P_ 2047

// -------- scratch (device globals; no allocations allowed) --------
__device__ float g_Q[(size_t)B_ * T_ * F_];          // 16 MB
__device__ float g_K[(size_t)B_ * T_ * F_];          // 16 MB
__device__ float g_V[(size_t)B_ * T_ * F_];          // 16 MB
__device__ float g_P[(size_t)(P_ + 1) * F_];         // ~4 MB
__device__ float g_S[(size_t)B_ * H_ * T_ * T_];     // 256 MB
__device__ float g_ctx[(size_t)B_ * T_ * F_];        // 16 MB

// =====================================================================
// Generic NT GEMM:  C[M,N] = A[M,K] @ W[N,K]^T (+ bias[N])
// 128x128 block tile, BK=16, 256 threads, 8x8 per thread.
// =====================================================================
__global__ void __launch_bounds__(256) gemm_nt_bias(
    const float* __restrict__ A, const float* __restrict__ W,
    const float* __restrict__ bias, float* __restrict__ C,
    int M, int N, int K)
{
    __shared__ __align__(16) float As[16][132];  // [k][m]
    __shared__ __align__(16) float Ws[16][132];  // [k][n]

    const int tid = threadIdx.x;
    const int tx = tid & 15;   // n direction
    const int ty = tid >> 4;   // m direction
    const int m0 = blockIdx.y * 128;
    const int n0 = blockIdx.x * 128;

    float acc[8][8];
#pragma unroll
    for (int i = 0; i < 8; i++)
#pragma unroll
        for (int j = 0; j < 8; j++) acc[i][j] = 0.f;

    for (int k0 = 0; k0 < K; k0 += 16) {
#pragma unroll
        for (int f = tid; f < 512; f += 256) {
            int r = f >> 2;
            int c = (f & 3) << 2;
            int gm = m0 + r; if (gm >= M) gm = M - 1;
            float4 a4 = *(const float4*)(A + (size_t)gm * K + k0 + c);
            As[c + 0][r] = a4.x; As[c + 1][r] = a4.y;
            As[c + 2][r] = a4.z; As[c + 3][r] = a4.w;
            int gn = n0 + r; if (gn >= N) gn = N - 1;
            float4 w4 = *(const float4*)(W + (size_t)gn * K + k0 + c);
            Ws[c + 0][r] = w4.x; Ws[c + 1][r] = w4.y;
            Ws[c + 2][r] = w4.z; Ws[c + 3][r] = w4.w;
        }
        __syncthreads();

#pragma unroll
        for (int kk = 0; kk < 16; kk++) {
            float4 ra0 = *(const float4*)&As[kk][ty * 8];
            float4 ra1 = *(const float4*)&As[kk][ty * 8 + 4];
            float4 rb0 = *(const float4*)&Ws[kk][tx * 8];
            float4 rb1 = *(const float4*)&Ws[kk][tx * 8 + 4];
            float ra[8] = {ra0.x, ra0.y, ra0.z, ra0.w, ra1.x, ra1.y, ra1.z, ra1.w};
            float rb[8] = {rb0.x, rb0.y, rb0.z, rb0.w, rb1.x, rb1.y, rb1.z, rb1.w};
#pragma unroll
            for (int i = 0; i < 8; i++)
#pragma unroll
                for (int j = 0; j < 8; j++)
                    acc[i][j] = fmaf(ra[i], rb[j], acc[i][j]);
        }
        __syncthreads();
    }

#pragma unroll
    for (int i = 0; i < 8; i++) {
        int gm = m0 + ty * 8 + i;
        if (gm >= M) continue;
#pragma unroll
        for (int j = 0; j < 8; j++) {
            int gn = n0 + tx * 8 + j;
            if (gn >= N) continue;
            float bv = bias ? bias[gn] : 0.f;
            C[(size_t)gm * N + gn] = acc[i][j] + bv;
        }
    }
}

// =====================================================================
// Fused scores:  S[b,h,t,s] = ( (q+u)·k[s] + (q+v)·p[T-1-t+s] ) / sqrt(DK)
// rel_shift folded into the p index. 64x64 tile per block, 4x4 / thread.
// =====================================================================
__global__ void __launch_bounds__(256) scores_kernel(
    const float* __restrict__ pu, const float* __restrict__ pv)
{
    __shared__ float qu[64][33];
    __shared__ float qv[64][33];
    __shared__ float ks[64][33];
    __shared__ float pw[127][33];

    const int tid = threadIdx.x;
    const int tx = tid & 15;   // s direction
    const int ty = tid >> 4;   // t direction
    const int bh = blockIdx.z;
    const int b = bh >> 3;
    const int h = bh & 7;
    const int t0 = blockIdx.y * 64;
    const int s0 = blockIdx.x * 64;
    const int rbase = (T_ - 1) - t0 - 63 + s0;  // >= 0, rbase+126 <= 2046
    const int base = 60 + tx * 4 - ty * 4;      // pw row offset index base

    float accA[4][4], accB[4][4];
#pragma unroll
    for (int i = 0; i < 4; i++)
#pragma unroll
        for (int j = 0; j < 4; j++) { accA[i][j] = 0.f; accB[i][j] = 0.f; }

    for (int dc = 0; dc < DK_; dc += 32) {
        // load q (make qu/qv), k tiles: 64 rows x 32 cols each
        for (int e = tid; e < 512; e += 256) {
            int r = e >> 3;
            int c = (e & 7) << 2;
            float4 q4 = *(const float4*)(g_Q + ((size_t)(b * T_ + t0 + r)) * F_ + h * DK_ + dc + c);
            float4 u4 = *(const float4*)(pu + h * DK_ + dc + c);
            float4 v4 = *(const float4*)(pv + h * DK_ + dc + c);
            qu[r][c + 0] = q4.x + u4.x; qu[r][c + 1] = q4.y + u4.y;
            qu[r][c + 2] = q4.z + u4.z; qu[r][c + 3] = q4.w + u4.w;
            qv[r][c + 0] = q4.x + v4.x; qv[r][c + 1] = q4.y + v4.y;
            qv[r][c + 2] = q4.z + v4.z; qv[r][c + 3] = q4.w + v4.w;
            float4 k4 = *(const float4*)(g_K + ((size_t)(b * T_ + s0 + r)) * F_ + h * DK_ + dc + c);
            ks[r][c + 0] = k4.x; ks[r][c + 1] = k4.y;
            ks[r][c + 2] = k4.z; ks[r][c + 3] = k4.w;
        }
        // load p window: 127 rows x 32 cols
        for (int e = tid; e < 1016; e += 256) {
            int r = e >> 3;
            int c = (e & 7) << 2;
            float4 p4 = *(const float4*)(g_P + (size_t)(rbase + r) * F_ + h * DK_ + dc + c);
            pw[r][c + 0] = p4.x; pw[r][c + 1] = p4.y;
            pw[r][c + 2] = p4.z; pw[r][c + 3] = p4.w;
        }
        __syncthreads();

#pragma unroll 8
        for (int d = 0; d < 32; d++) {
            float a[4], bb[4], kr[4], pr[7];
#pragma unroll
            for (int i = 0; i < 4; i++) {
                a[i] = qu[ty * 4 + i][d];
                bb[i] = qv[ty * 4 + i][d];
            }
#pragma unroll
            for (int j = 0; j < 4; j++) kr[j] = ks[tx * 4 + j][d];
#pragma unroll
            for (int m = 0; m < 7; m++) pr[m] = pw[base + m][d];
#pragma unroll
            for (int i = 0; i < 4; i++)
#pragma unroll
                for (int j = 0; j < 4; j++) {
                    accA[i][j] = fmaf(a[i], kr[j], accA[i][j]);
                    accB[i][j] = fmaf(bb[i], pr[j - i + 3], accB[i][j]);
                }
        }
        __syncthreads();
    }

#pragma unroll
    for (int i = 0; i < 4; i++) {
        size_t row = ((size_t)bh * T_ + t0 + ty * 4 + i) * T_ + s0 + tx * 4;
        float4 o;
        o.x = (accA[i][0] + accB[i][0]) * 0.125f;
        o.y = (accA[i][1] + accB[i][1]) * 0.125f;
        o.z = (accA[i][2] + accB[i][2]) * 0.125f;
        o.w = (accA[i][3] + accB[i][3]) * 0.125f;
        *(float4*)(g_S + row) = o;
    }
}

// =====================================================================
// Masked softmax over last dim (T=1024). One block per row, 256 threads.
// =====================================================================
__global__ void __launch_bounds__(256) softmax_kernel(const int* __restrict__ mask)
{
    const int row = blockIdx.x;           // bh*T + t
    const int b = row >> 13;              // / (H*T)
    float* srow = g_S + (size_t)row * T_;
    const int* mrow = mask + b * T_;

    __shared__ float red[8];
    const int tid = threadIdx.x;
    const int lane = tid & 31;
    const int warp = tid >> 5;
    const float NEG = -3.402823466e38f;

    float vals[4];
    float mx = NEG;
#pragma unroll
    for (int q = 0; q < 4; q++) {
        int s = tid + q * 256;
        float x = srow[s];
        if (mrow[s] == 0) x = NEG;
        vals[q] = x;
        mx = fmaxf(mx, x);
    }
#pragma unroll
    for (int o = 16; o > 0; o >>= 1) mx = fmaxf(mx, __shfl_xor_sync(0xffffffffu, mx, o));
    if (lane == 0) red[warp] = mx;
    __syncthreads();
    float mall = red[0];
#pragma unroll
    for (int w = 1; w < 8; w++) mall = fmaxf(mall, red[w]);
    __syncthreads();

    float sum = 0.f;
#pragma unroll
    for (int q = 0; q < 4; q++) {
        float e = __expf(vals[q] - mall);
        vals[q] = e;
        sum += e;
    }
#pragma unroll
    for (int o = 16; o > 0; o >>= 1) sum += __shfl_xor_sync(0xffffffffu, sum, o);
    if (lane == 0) red[warp] = sum;
    __syncthreads();
    float tot = red[0];
#pragma unroll
    for (int w = 1; w < 8; w++) tot += red[w];
    float inv = 1.f / tot;

#pragma unroll
    for (int q = 0; q < 4; q++) {
        int s = tid + q * 256;
        float o = vals[q] * inv;
        if (mrow[s] == 0) o = 0.f;
        srow[s] = o;
    }
}

// =====================================================================
// ctx[b,t,h*64+d] = sum_s attn[b,h,t,s] * V[b,s,h*64+d]
// 64 (t) x 64 (d) tile per block, s in chunks of 64. 4x4 per thread.
// =====================================================================
__global__ void __launch_bounds__(256) av_kernel()
{
    __shared__ __align__(16) float as[64][68];
    __shared__ __align__(16) float vs[64][68];

    const int tid = threadIdx.x;
    const int tx = tid & 15;   // d direction
    const int ty = tid >> 4;   // t direction
    const int bh = blockIdx.y;
    const int b = bh >> 3;
    const int h = bh & 7;
    const int t0 = blockIdx.x * 64;

    float acc[4][4];
#pragma unroll
    for (int i = 0; i < 4; i++)
#pragma unroll
        for (int j = 0; j < 4; j++) acc[i][j] = 0.f;

    for (int s0 = 0; s0 < T_; s0 += 64) {
        for (int f = tid; f < 1024; f += 256) {
            int r = f >> 4;
            int c = (f & 15) << 2;
            *(float4*)&as[r][c] =
                *(const float4*)(g_S + ((size_t)bh * T_ + t0 + r) * T_ + s0 + c);
            *(float4*)&vs[r][c] =
                *(const float4*)(g_V + ((size_t)(b * T_ + s0 + r)) * F_ + h * DK_ + c);
        }
        __syncthreads();

#pragma unroll 4
        for (int s4 = 0; s4 < 64; s4 += 4) {
            float aa[4][4], av[4][4];
#pragma unroll
            for (int i = 0; i < 4; i++) {
                float4 t4 = *(const float4*)&as[ty * 4 + i][s4];
                aa[i][0] = t4.x; aa[i][1] = t4.y; aa[i][2] = t4.z; aa[i][3] = t4.w;
            }
#pragma unroll
            for (int q = 0; q < 4; q++) {
                float4 t4 = *(const float4*)&vs[s4 + q][tx * 4];
                av[q][0] = t4.x; av[q][1] = t4.y; av[q][2] = t4.z; av[q][3] = t4.w;
            }
#pragma unroll
            for (int i = 0; i < 4; i++)
#pragma unroll
                for (int j = 0; j < 4; j++) {
                    acc[i][j] = fmaf(aa[i][0], av[0][j], acc[i][j]);
                    acc[i][j] = fmaf(aa[i][1], av[1][j], acc[i][j]);
                    acc[i][j] = fmaf(aa[i][2], av[2][j], acc[i][j]);
                    acc[i][j] = fmaf(aa[i][3], av[3][j], acc[i][j]);
                }
        }
        __syncthreads();
    }

#pragma unroll
    for (int i = 0; i < 4; i++) {
        size_t row = ((size_t)(b * T_ + t0 + ty * 4 + i)) * F_ + h * DK_ + tx * 4;
        float4 o;
        o.x = acc[i][0]; o.y = acc[i][1]; o.z = acc[i][2]; o.w = acc[i][3];
        *(float4*)(g_ctx + row) = o;
    }
}

// =====================================================================
extern "C" void kernel_launch(void* const* d_in, const int* in_sizes, int n_in,
                              void* d_out, int out_size)
{
    const float* query   = (const float*)d_in[0];
    const float* key_in  = (const float*)d_in[1];
    const float* value   = (const float*)d_in[2];
    const float* pos_emb = (const float*)d_in[3];
    const int*   mask    = (const int*)d_in[4];
    const float* Wq = (const float*)d_in[5];
    const float* bq = (const float*)d_in[6];
    const float* Wk = (const float*)d_in[7];
    const float* bk = (const float*)d_in[8];
    const float* Wv = (const float*)d_in[9];
    const float* bv = (const float*)d_in[10];
    const float* Wo = (const float*)d_in[11];
    const float* bo = (const float*)d_in[12];
    const float* Wp = (const float*)d_in[13];
    const float* pu = (const float*)d_in[14];
    const float* pv = (const float*)d_in[15];
    float* out = (float*)d_out;

    float *Qp, *Kp, *Vp, *Pq, *Cp;
    cudaGetSymbolAddress((void**)&Qp, g_Q);
    cudaGetSymbolAddress((void**)&Kp, g_K);
    cudaGetSymbolAddress((void**)&Vp, g_V);
    cudaGetSymbolAddress((void**)&Pq, g_P);
    cudaGetSymbolAddress((void**)&Cp, g_ctx);

    dim3 blk(256);

    // projections: [8192,512] @ [512,512]^T
    gemm_nt_bias<<<dim3(4, 64), blk>>>(query,  Wq, bq, Qp, B_ * T_, F_, F_);
    gemm_nt_bias<<<dim3(4, 64), blk>>>(key_in, Wk, bk, Kp, B_ * T_, F_, F_);
    gemm_nt_bias<<<dim3(4, 64), blk>>>(value,  Wv, bv, Vp, B_ * T_, F_, F_);
    // positional projection: [2047,512] @ [512,512]^T (no bias)
    gemm_nt_bias<<<dim3(4, 16), blk>>>(pos_emb, Wp, nullptr, Pq, P_, F_, F_);

    // fused AC + rel-shifted BD scores
    scores_kernel<<<dim3(16, 16, B_ * H_), blk>>>(pu, pv);

    // masked softmax
    softmax_kernel<<<dim3(B_ * H_ * T_), blk>>>(mask);

    // attn @ V
    av_kernel<<<dim3(16, B_ * H_), blk>>>();

    // output projection
    gemm_nt_bias<<<dim3(4, 64), blk>>>(Cp, Wo, bo, out, B_ * T_, F_, F_);
}

// round 3
// speedup vs baseline: 1.1007x; 1.1007x over previous
#include <cuda_runtime.h>
#include <cuda_bf16.h>
#include <math.h>

#define B_ 8
#define T_ 1024
#define F_ 512
#define H_ 8
#define DK_ 64
#define P_ 2047

// -------- scratch (device globals; no allocations allowed) --------
__device__ float g_Q[(size_t)B_ * T_ * F_];          // 16 MB
__device__ float g_K[(size_t)B_ * T_ * F_];          // 16 MB
__device__ float g_V[(size_t)B_ * T_ * F_];          // 16 MB
__device__ float g_P[(size_t)(P_ + 1) * F_];         // ~4 MB
__device__ float g_S[(size_t)B_ * H_ * T_ * T_];     // 256 MB
__device__ float g_ctx[(size_t)B_ * T_ * F_];        // 16 MB

// =====================================================================
// Tensor-core helpers (legacy mma.sync path, bf16, fp32 accumulate)
// =====================================================================
__device__ __forceinline__ unsigned smem_u32(const void* p) {
    return (unsigned)__cvta_generic_to_shared(p);
}

__device__ __forceinline__ void ldsm_x4(unsigned addr, unsigned& r0, unsigned& r1,
                                        unsigned& r2, unsigned& r3) {
    asm volatile("ldmatrix.sync.aligned.m8n8.x4.shared.b16 {%0,%1,%2,%3}, [%4];"
                 : "=r"(r0), "=r"(r1), "=r"(r2), "=r"(r3) : "r"(addr));
}

__device__ __forceinline__ void ldsm_x2(unsigned addr, unsigned& r0, unsigned& r1) {
    asm volatile("ldmatrix.sync.aligned.m8n8.x2.shared.b16 {%0,%1}, [%2];"
                 : "=r"(r0), "=r"(r1) : "r"(addr));
}

__device__ __forceinline__ void mma_bf16(float& c0, float& c1, float& c2, float& c3,
                                         unsigned a0, unsigned a1, unsigned a2, unsigned a3,
                                         unsigned b0, unsigned b1) {
    asm volatile(
        "mma.sync.aligned.m16n8k16.row.col.f32.bf16.bf16.f32 "
        "{%0,%1,%2,%3},{%4,%5,%6,%7},{%8,%9},{%0,%1,%2,%3};"
        : "+f"(c0), "+f"(c1), "+f"(c2), "+f"(c3)
        : "r"(a0), "r"(a1), "r"(a2), "r"(a3), "r"(b0), "r"(b1));
}

// split fp32 float4 into bf16 hi/lo and store 4 contiguous elements
__device__ __forceinline__ void cvt4(__nv_bfloat16* dh, __nv_bfloat16* dl, float4 v) {
    float f[4] = {v.x, v.y, v.z, v.w};
#pragma unroll
    for (int i = 0; i < 4; i++) {
        __nv_bfloat16 h = __float2bfloat16(f[i]);
        dh[i] = h;
        dl[i] = __float2bfloat16(f[i] - __bfloat162float(h));
    }
}

// =====================================================================
// bf16x3 tensor-core NT GEMM:  C[M,N] = A[M,K] @ W[N,K]^T (+ bias[N])
// 128x128 block tile, BK=32, 256 threads, warp tile 64x32 (2x4 warps),
// per warp 4x4 m16n8k16 fragments, 3 MMAs per fragment (hi/lo split).
// =====================================================================
#define BK_ 32
#define LDSA (BK_ + 8)   // 40 halves per row = 80B stride (conflict-free ldmatrix)

__global__ void __launch_bounds__(256) gemm_bf16x3(
    const float* __restrict__ A, const float* __restrict__ W,
    const float* __restrict__ bias, float* __restrict__ C,
    int M, int N, int K)
{
    __shared__ __nv_bfloat16 Ah[128][LDSA], Al[128][LDSA];
    __shared__ __nv_bfloat16 Wh[128][LDSA], Wl[128][LDSA];

    const int tid = threadIdx.x;
    const int lane = tid & 31;
    const int warp = tid >> 5;
    const int wm = warp & 1;        // 2 warps along m
    const int wn = warp >> 1;       // 4 warps along n
    const int m0 = blockIdx.y * 128;
    const int n0 = blockIdx.x * 128;

    // ldmatrix lane mappings
    const int arow = lane & 15;
    const int asel = (lane >> 4) << 3;          // 0 or 8 (k sub-block)
    const int bn_off = lane & 7;
    const int bsel = ((lane >> 3) & 1) << 3;    // 0 or 8

    float acc[4][4][4];
#pragma unroll
    for (int i = 0; i < 4; i++)
#pragma unroll
        for (int j = 0; j < 4; j++)
#pragma unroll
            for (int q = 0; q < 4; q++) acc[i][j][q] = 0.f;

    for (int k0 = 0; k0 < K; k0 += BK_) {
        // global -> smem with fp32 -> (bf16 hi, bf16 lo) split
#pragma unroll
        for (int q = 0; q < 4; q++) {
            int idx = tid + q * 256;       // 0..1023
            int row = idx >> 3;            // 0..127
            int col = (idx & 7) << 2;      // 0,4,...,28
            int gm = m0 + row; if (gm >= M) gm = M - 1;
            float4 a4 = *(const float4*)(A + (size_t)gm * K + k0 + col);
            cvt4(&Ah[row][col], &Al[row][col], a4);
            int gn = n0 + row; if (gn >= N) gn = N - 1;
            float4 w4 = *(const float4*)(W + (size_t)gn * K + k0 + col);
            cvt4(&Wh[row][col], &Wl[row][col], w4);
        }
        __syncthreads();

#pragma unroll
        for (int kk = 0; kk < 2; kk++) {
            const int kb = kk << 4;
            unsigned ah[4][4], al[4][4], bh[4][2], bl[4][2];
#pragma unroll
            for (int i = 0; i < 4; i++) {
                int r = wm * 64 + i * 16 + arow;
                ldsm_x4(smem_u32(&Ah[r][kb + asel]), ah[i][0], ah[i][1], ah[i][2], ah[i][3]);
                ldsm_x4(smem_u32(&Al[r][kb + asel]), al[i][0], al[i][1], al[i][2], al[i][3]);
            }
#pragma unroll
            for (int j = 0; j < 4; j++) {
                int n = wn * 32 + j * 8 + bn_off;
                ldsm_x2(smem_u32(&Wh[n][kb + bsel]), bh[j][0], bh[j][1]);
                ldsm_x2(smem_u32(&Wl[n][kb + bsel]), bl[j][0], bl[j][1]);
            }
#pragma unroll
            for (int i = 0; i < 4; i++)
#pragma unroll
                for (int j = 0; j < 4; j++) {
                    mma_bf16(acc[i][j][0], acc[i][j][1], acc[i][j][2], acc[i][j][3],
                             ah[i][0], ah[i][1], ah[i][2], ah[i][3], bh[j][0], bh[j][1]);
                    mma_bf16(acc[i][j][0], acc[i][j][1], acc[i][j][2], acc[i][j][3],
                             ah[i][0], ah[i][1], ah[i][2], ah[i][3], bl[j][0], bl[j][1]);
                    mma_bf16(acc[i][j][0], acc[i][j][1], acc[i][j][2], acc[i][j][3],
                             al[i][0], al[i][1], al[i][2], al[i][3], bh[j][0], bh[j][1]);
                }
        }
        __syncthreads();
    }

    // epilogue: fragment layout c0,c1 -> (m, n..n+1), c2,c3 -> (m+8, n..n+1)
#pragma unroll
    for (int i = 0; i < 4; i++) {
        int m = m0 + wm * 64 + i * 16 + (lane >> 2);
#pragma unroll
        for (int j = 0; j < 4; j++) {
            int n = n0 + wn * 32 + j * 8 + (lane & 3) * 2;
            float bb0 = bias ? bias[n] : 0.f;
            float bb1 = bias ? bias[n + 1] : 0.f;
            if (m < M) {
                C[(size_t)m * N + n]     = acc[i][j][0] + bb0;
                C[(size_t)m * N + n + 1] = acc[i][j][1] + bb1;
            }
            if (m + 8 < M) {
                C[(size_t)(m + 8) * N + n]     = acc[i][j][2] + bb0;
                C[(size_t)(m + 8) * N + n + 1] = acc[i][j][3] + bb1;
            }
        }
    }
}

// =====================================================================
// Fused scores:  S[b,h,t,s] = ( (q+u)·k[s] + (q+v)·p[T-1-t+s] ) / sqrt(DK)
// rel_shift folded into the p index. 64x64 tile per block, 4x4 / thread.
// =====================================================================
__global__ void __launch_bounds__(256) scores_kernel(
    const float* __restrict__ pu, const float* __restrict__ pv)
{
    __shared__ float qu[64][33];
    __shared__ float qv[64][33];
    __shared__ float ks[64][33];
    __shared__ float pw[127][33];

    const int tid = threadIdx.x;
    const int tx = tid & 15;   // s direction
    const int ty = tid >> 4;   // t direction
    const int bh = blockIdx.z;
    const int b = bh >> 3;
    const int h = bh & 7;
    const int t0 = blockIdx.y * 64;
    const int s0 = blockIdx.x * 64;
    const int rbase = (T_ - 1) - t0 - 63 + s0;
    const int base = 60 + tx * 4 - ty * 4;

    float accA[4][4], accB[4][4];
#pragma unroll
    for (int i = 0; i < 4; i++)
#pragma unroll
        for (int j = 0; j < 4; j++) { accA[i][j] = 0.f; accB[i][j] = 0.f; }

    for (int dc = 0; dc < DK_; dc += 32) {
        for (int e = tid; e < 512; e += 256) {
            int r = e >> 3;
            int c = (e & 7) << 2;
            float4 q4 = *(const float4*)(g_Q + ((size_t)(b * T_ + t0 + r)) * F_ + h * DK_ + dc + c);
            float4 u4 = *(const float4*)(pu + h * DK_ + dc + c);
            float4 v4 = *(const float4*)(pv + h * DK_ + dc + c);
            qu[r][c + 0] = q4.x + u4.x; qu[r][c + 1] = q4.y + u4.y;
            qu[r][c + 2] = q4.z + u4.z; qu[r][c + 3] = q4.w + u4.w;
            qv[r][c + 0] = q4.x + v4.x; qv[r][c + 1] = q4.y + v4.y;
            qv[r][c + 2] = q4.z + v4.z; qv[r][c + 3] = q4.w + v4.w;
            float4 k4 = *(const float4*)(g_K + ((size_t)(b * T_ + s0 + r)) * F_ + h * DK_ + dc + c);
            ks[r][c + 0] = k4.x; ks[r][c + 1] = k4.y;
            ks[r][c + 2] = k4.z; ks[r][c + 3] = k4.w;
        }
        for (int e = tid; e < 1016; e += 256) {
            int r = e >> 3;
            int c = (e & 7) << 2;
            float4 p4 = *(const float4*)(g_P + (size_t)(rbase + r) * F_ + h * DK_ + dc + c);
            pw[r][c + 0] = p4.x; pw[r][c + 1] = p4.y;
            pw[r][c + 2] = p4.z; pw[r][c + 3] = p4.w;
        }
        __syncthreads();

#pragma unroll 8
        for (int d = 0; d < 32; d++) {
            float a[4], bb[4], kr[4], pr[7];
#pragma unroll
            for (int i = 0; i < 4; i++) {
                a[i] = qu[ty * 4 + i][d];
                bb[i] = qv[ty * 4 + i][d];
            }
#pragma unroll
            for (int j = 0; j < 4; j++) kr[j] = ks[tx * 4 + j][d];
#pragma unroll
            for (int m = 0; m < 7; m++) pr[m] = pw[base + m][d];
#pragma unroll
            for (int i = 0; i < 4; i++)
#pragma unroll
                for (int j = 0; j < 4; j++) {
                    accA[i][j] = fmaf(a[i], kr[j], accA[i][j]);
                    accB[i][j] = fmaf(bb[i], pr[j - i + 3], accB[i][j]);
                }
        }
        __syncthreads();
    }

#pragma unroll
    for (int i = 0; i < 4; i++) {
        size_t row = ((size_t)bh * T_ + t0 + ty * 4 + i) * T_ + s0 + tx * 4;
        float4 o;
        o.x = (accA[i][0] + accB[i][0]) * 0.125f;
        o.y = (accA[i][1] + accB[i][1]) * 0.125f;
        o.z = (accA[i][2] + accB[i][2]) * 0.125f;
        o.w = (accA[i][3] + accB[i][3]) * 0.125f;
        *(float4*)(g_S + row) = o;
    }
}

// =====================================================================
// Masked softmax over last dim (T=1024). One block per row, 256 threads.
// =====================================================================
__global__ void __launch_bounds__(256) softmax_kernel(const int* __restrict__ mask)
{
    const int row = blockIdx.x;
    const int b = row >> 13;
    float* srow = g_S + (size_t)row * T_;
    const int* mrow = mask + b * T_;

    __shared__ float red[8];
    const int tid = threadIdx.x;
    const int lane = tid & 31;
    const int warp = tid >> 5;
    const float NEG = -3.402823466e38f;

    float vals[4];
    float mx = NEG;
#pragma unroll
    for (int q = 0; q < 4; q++) {
        int s = tid + q * 256;
        float x = srow[s];
        if (mrow[s] == 0) x = NEG;
        vals[q] = x;
        mx = fmaxf(mx, x);
    }
#pragma unroll
    for (int o = 16; o > 0; o >>= 1) mx = fmaxf(mx, __shfl_xor_sync(0xffffffffu, mx, o));
    if (lane == 0) red[warp] = mx;
    __syncthreads();
    float mall = red[0];
#pragma unroll
    for (int w = 1; w < 8; w++) mall = fmaxf(mall, red[w]);
    __syncthreads();

    float sum = 0.f;
#pragma unroll
    for (int q = 0; q < 4; q++) {
        float e = __expf(vals[q] - mall);
        vals[q] = e;
        sum += e;
    }
#pragma unroll
    for (int o = 16; o > 0; o >>= 1) sum += __shfl_xor_sync(0xffffffffu, sum, o);
    if (lane == 0) red[warp] = sum;
    __syncthreads();
    float tot = red[0];
#pragma unroll
    for (int w = 1; w < 8; w++) tot += red[w];
    float inv = 1.f / tot;

#pragma unroll
    for (int q = 0; q < 4; q++) {
        int s = tid + q * 256;
        float o = vals[q] * inv;
        if (mrow[s] == 0) o = 0.f;
        srow[s] = o;
    }
}

// =====================================================================
// ctx[b,t,h*64+d] = sum_s attn[b,h,t,s] * V[b,s,h*64+d]
// 64 (t) x 64 (d) tile per block, s in chunks of 64. 4x4 per thread.
// =====================================================================
__global__ void __launch_bounds__(256) av_kernel()
{
    __shared__ __align__(16) float as[64][68];
    __shared__ __align__(16) float vs[64][68];

    const int tid = threadIdx.x;
    const int tx = tid & 15;   // d direction
    const int ty = tid >> 4;   // t direction
    const int bh = blockIdx.y;
    const int b = bh >> 3;
    const int h = bh & 7;
    const int t0 = blockIdx.x * 64;

    float acc[4][4];
#pragma unroll
    for (int i = 0; i < 4; i++)
#pragma unroll
        for (int j = 0; j < 4; j++) acc[i][j] = 0.f;

    for (int s0 = 0; s0 < T_; s0 += 64) {
        for (int f = tid; f < 1024; f += 256) {
            int r = f >> 4;
            int c = (f & 15) << 2;
            *(float4*)&as[r][c] =
                *(const float4*)(g_S + ((size_t)bh * T_ + t0 + r) * T_ + s0 + c);
            *(float4*)&vs[r][c] =
                *(const float4*)(g_V + ((size_t)(b * T_ + s0 + r)) * F_ + h * DK_ + c);
        }
        __syncthreads();

#pragma unroll 4
        for (int s4 = 0; s4 < 64; s4 += 4) {
            float aa[4][4], av[4][4];
#pragma unroll
            for (int i = 0; i < 4; i++) {
                float4 t4 = *(const float4*)&as[ty * 4 + i][s4];
                aa[i][0] = t4.x; aa[i][1] = t4.y; aa[i][2] = t4.z; aa[i][3] = t4.w;
            }
#pragma unroll
            for (int q = 0; q < 4; q++) {
                float4 t4 = *(const float4*)&vs[s4 + q][tx * 4];
                av[q][0] = t4.x; av[q][1] = t4.y; av[q][2] = t4.z; av[q][3] = t4.w;
            }
#pragma unroll
            for (int i = 0; i < 4; i++)
#pragma unroll
                for (int j = 0; j < 4; j++) {
                    acc[i][j] = fmaf(aa[i][0], av[0][j], acc[i][j]);
                    acc[i][j] = fmaf(aa[i][1], av[1][j], acc[i][j]);
                    acc[i][j] = fmaf(aa[i][2], av[2][j], acc[i][j]);
                    acc[i][j] = fmaf(aa[i][3], av[3][j], acc[i][j]);
                }
        }
        __syncthreads();
    }

#pragma unroll
    for (int i = 0; i < 4; i++) {
        size_t row = ((size_t)(b * T_ + t0 + ty * 4 + i)) * F_ + h * DK_ + tx * 4;
        float4 o;
        o.x = acc[i][0]; o.y = acc[i][1]; o.z = acc[i][2]; o.w = acc[i][3];
        *(float4*)(g_ctx + row) = o;
    }
}

// =====================================================================
extern "C" void kernel_launch(void* const* d_in, const int* in_sizes, int n_in,
                              void* d_out, int out_size)
{
    const float* query   = (const float*)d_in[0];
    const float* key_in  = (const float*)d_in[1];
    const float* value   = (const float*)d_in[2];
    const float* pos_emb = (const float*)d_in[3];
    const int*   mask    = (const int*)d_in[4];
    const float* Wq = (const float*)d_in[5];
    const float* bq = (const float*)d_in[6];
    const float* Wk = (const float*)d_in[7];
    const float* bk = (const float*)d_in[8];
    const float* Wv = (const float*)d_in[9];
    const float* bv = (const float*)d_in[10];
    const float* Wo = (const float*)d_in[11];
    const float* bo = (const float*)d_in[12];
    const float* Wp = (const float*)d_in[13];
    const float* pu = (const float*)d_in[14];
    const float* pv = (const float*)d_in[15];
    float* out = (float*)d_out;

    float *Qp, *Kp, *Vp, *Pq, *Cp;
    cudaGetSymbolAddress((void**)&Qp, g_Q);
    cudaGetSymbolAddress((void**)&Kp, g_K);
    cudaGetSymbolAddress((void**)&Vp, g_V);
    cudaGetSymbolAddress((void**)&Pq, g_P);
    cudaGetSymbolAddress((void**)&Cp, g_ctx);

    dim3 blk(256);

    // projections via bf16x3 tensor-core GEMM: [8192,512] @ [512,512]^T
    gemm_bf16x3<<<dim3(4, 64), blk>>>(query,  Wq, bq, Qp, B_ * T_, F_, F_);
    gemm_bf16x3<<<dim3(4, 64), blk>>>(key_in, Wk, bk, Kp, B_ * T_, F_, F_);
    gemm_bf16x3<<<dim3(4, 64), blk>>>(value,  Wv, bv, Vp, B_ * T_, F_, F_);
    // positional projection: [2047,512] @ [512,512]^T (no bias)
    gemm_bf16x3<<<dim3(4, 16), blk>>>(pos_emb, Wp, nullptr, Pq, P_, F_, F_);

    // fused AC + rel-shifted BD scores
    scores_kernel<<<dim3(16, 16, B_ * H_), blk>>>(pu, pv);

    // masked softmax
    softmax_kernel<<<dim3(B_ * H_ * T_), blk>>>(mask);

    // attn @ V
    av_kernel<<<dim3(16, B_ * H_), blk>>>();

    // output projection
    gemm_bf16x3<<<dim3(4, 64), blk>>>(Cp, Wo, bo, out, B_ * T_, F_, F_);
}

// round 4
// speedup vs baseline: 2.5287x; 2.2972x over previous
#include <cuda_runtime.h>
#include <cuda_bf16.h>
#include <math.h>

#define B_ 8
#define T_ 1024
#define F_ 512
#define H_ 8
#define DK_ 64
#define P_ 2047

// -------- scratch (device globals; no allocations allowed) --------
__device__ float g_Q[(size_t)B_ * T_ * F_];                 // fp32 q proj
__device__ __nv_bfloat16 g_Kh[(size_t)B_ * T_ * F_];        // k hi
__device__ __nv_bfloat16 g_Kl[(size_t)B_ * T_ * F_];        // k lo
__device__ __nv_bfloat16 g_Vth[(size_t)B_ * H_ * DK_ * T_]; // v^T hi  [b,h,d,s]
__device__ __nv_bfloat16 g_Vtl[(size_t)B_ * H_ * DK_ * T_]; // v^T lo
__device__ __nv_bfloat16 g_Ph[(size_t)(P_ + 1) * F_];       // p hi (row 2047 = 0)
__device__ __nv_bfloat16 g_Pl[(size_t)(P_ + 1) * F_];       // p lo
__device__ float g_ctx[(size_t)B_ * T_ * F_];

// =====================================================================
// Tensor-core helpers
// =====================================================================
__device__ __forceinline__ unsigned smem_u32(const void* p) {
    return (unsigned)__cvta_generic_to_shared(p);
}

__device__ __forceinline__ void ldsm_x4(unsigned addr, unsigned& r0, unsigned& r1,
                                        unsigned& r2, unsigned& r3) {
    asm volatile("ldmatrix.sync.aligned.m8n8.x4.shared.b16 {%0,%1,%2,%3}, [%4];"
                 : "=r"(r0), "=r"(r1), "=r"(r2), "=r"(r3) : "r"(addr));
}

__device__ __forceinline__ void ldsm_x2(unsigned addr, unsigned& r0, unsigned& r1) {
    asm volatile("ldmatrix.sync.aligned.m8n8.x2.shared.b16 {%0,%1}, [%2];"
                 : "=r"(r0), "=r"(r1) : "r"(addr));
}

__device__ __forceinline__ void mma_bf16(float& c0, float& c1, float& c2, float& c3,
                                         unsigned a0, unsigned a1, unsigned a2, unsigned a3,
                                         unsigned b0, unsigned b1) {
    asm volatile(
        "mma.sync.aligned.m16n8k16.row.col.f32.bf16.bf16.f32 "
        "{%0,%1,%2,%3},{%4,%5,%6,%7},{%8,%9},{%0,%1,%2,%3};"
        : "+f"(c0), "+f"(c1), "+f"(c2), "+f"(c3)
        : "r"(a0), "r"(a1), "r"(a2), "r"(a3), "r"(b0), "r"(b1));
}

__device__ __forceinline__ void split_hl(float x, __nv_bfloat16& h, __nv_bfloat16& l) {
    h = __float2bfloat16(x);
    l = __float2bfloat16(x - __bfloat162float(h));
}

__device__ __forceinline__ void pack_hl(float x0, float x1, unsigned& hi, unsigned& lo) {
    __nv_bfloat16 h0, l0, h1, l1;
    split_hl(x0, h0, l0);
    split_hl(x1, h1, l1);
    hi = ((unsigned)__bfloat16_as_ushort(h1) << 16) | (unsigned)__bfloat16_as_ushort(h0);
    lo = ((unsigned)__bfloat16_as_ushort(l1) << 16) | (unsigned)__bfloat16_as_ushort(l0);
}

__device__ __forceinline__ void cvt4(__nv_bfloat16* dh, __nv_bfloat16* dl, float4 v) {
    float f[4] = {v.x, v.y, v.z, v.w};
#pragma unroll
    for (int i = 0; i < 4; i++) split_hl(f[i], dh[i], dl[i]);
}

// =====================================================================
// bf16x3 tensor-core NT GEMM:  C = A[M,K] @ W[N,K]^T (+ bias)
// mode 0: fp32 out to C.  mode 1: bf16 hi/lo out to (Ch, Cl).
// mode 2: bf16 hi/lo out TRANSPOSED per-head: dst[((b*H+h)*64+d)*T + s]
// =====================================================================
#define BK_ 32
#define LDSA (BK_ + 8)

__global__ void __launch_bounds__(256) gemm_bf16x3(
    const float* __restrict__ A, const float* __restrict__ W,
    const float* __restrict__ bias, float* __restrict__ C,
    __nv_bfloat16* __restrict__ Ch, __nv_bfloat16* __restrict__ Cl,
    int M, int N, int K, int mode)
{
    __shared__ __nv_bfloat16 Ah[128][LDSA], Al[128][LDSA];
    __shared__ __nv_bfloat16 Wh[128][LDSA], Wl[128][LDSA];

    const int tid = threadIdx.x;
    const int lane = tid & 31;
    const int warp = tid >> 5;
    const int wm = warp & 1;
    const int wn = warp >> 1;
    const int m0 = blockIdx.y * 128;
    const int n0 = blockIdx.x * 128;

    const int arow = lane & 15;
    const int asel = (lane >> 4) << 3;
    const int bn_off = lane & 7;
    const int bsel = ((lane >> 3) & 1) << 3;

    float acc[4][4][4];
#pragma unroll
    for (int i = 0; i < 4; i++)
#pragma unroll
        for (int j = 0; j < 4; j++)
#pragma unroll
            for (int q = 0; q < 4; q++) acc[i][j][q] = 0.f;

    for (int k0 = 0; k0 < K; k0 += BK_) {
#pragma unroll
        for (int q = 0; q < 4; q++) {
            int idx = tid + q * 256;
            int row = idx >> 3;
            int col = (idx & 7) << 2;
            int gm = m0 + row; if (gm >= M) gm = M - 1;
            float4 a4 = *(const float4*)(A + (size_t)gm * K + k0 + col);
            cvt4(&Ah[row][col], &Al[row][col], a4);
            int gn = n0 + row; if (gn >= N) gn = N - 1;
            float4 w4 = *(const float4*)(W + (size_t)gn * K + k0 + col);
            cvt4(&Wh[row][col], &Wl[row][col], w4);
        }
        __syncthreads();

#pragma unroll
        for (int kk = 0; kk < 2; kk++) {
            const int kb = kk << 4;
            unsigned ah[4][4], al[4][4], bh[4][2], bl[4][2];
#pragma unroll
            for (int i = 0; i < 4; i++) {
                int r = wm * 64 + i * 16 + arow;
                ldsm_x4(smem_u32(&Ah[r][kb + asel]), ah[i][0], ah[i][1], ah[i][2], ah[i][3]);
                ldsm_x4(smem_u32(&Al[r][kb + asel]), al[i][0], al[i][1], al[i][2], al[i][3]);
            }
#pragma unroll
            for (int j = 0; j < 4; j++) {
                int n = wn * 32 + j * 8 + bn_off;
                ldsm_x2(smem_u32(&Wh[n][kb + bsel]), bh[j][0], bh[j][1]);
                ldsm_x2(smem_u32(&Wl[n][kb + bsel]), bl[j][0], bl[j][1]);
            }
#pragma unroll
            for (int i = 0; i < 4; i++)
#pragma unroll
                for (int j = 0; j < 4; j++) {
                    mma_bf16(acc[i][j][0], acc[i][j][1], acc[i][j][2], acc[i][j][3],
                             ah[i][0], ah[i][1], ah[i][2], ah[i][3], bh[j][0], bh[j][1]);
                    mma_bf16(acc[i][j][0], acc[i][j][1], acc[i][j][2], acc[i][j][3],
                             ah[i][0], ah[i][1], ah[i][2], ah[i][3], bl[j][0], bl[j][1]);
                    mma_bf16(acc[i][j][0], acc[i][j][1], acc[i][j][2], acc[i][j][3],
                             al[i][0], al[i][1], al[i][2], al[i][3], bh[j][0], bh[j][1]);
                }
        }
        __syncthreads();
    }

#pragma unroll
    for (int i = 0; i < 4; i++) {
        int mbase = m0 + wm * 64 + i * 16 + (lane >> 2);
#pragma unroll
        for (int j = 0; j < 4; j++) {
            int n = n0 + wn * 32 + j * 8 + (lane & 3) * 2;
            float bb0 = bias ? bias[n] : 0.f;
            float bb1 = bias ? bias[n + 1] : 0.f;
#pragma unroll
            for (int half = 0; half < 2; half++) {
                int m = mbase + half * 8;
                if (m >= M) continue;
                float v0 = acc[i][j][half * 2 + 0] + bb0;
                float v1 = acc[i][j][half * 2 + 1] + bb1;
                if (mode == 0) {
                    C[(size_t)m * N + n] = v0;
                    C[(size_t)m * N + n + 1] = v1;
                } else if (mode == 1) {
                    __nv_bfloat16 h0, l0, h1, l1;
                    split_hl(v0, h0, l0); split_hl(v1, h1, l1);
                    Ch[(size_t)m * N + n] = h0; Cl[(size_t)m * N + n] = l0;
                    Ch[(size_t)m * N + n + 1] = h1; Cl[(size_t)m * N + n + 1] = l1;
                } else {
                    int bb = m >> 10, ss = m & 1023;
#pragma unroll
                    for (int e = 0; e < 2; e++) {
                        int nn = n + e;
                        int hh = nn >> 6, dd = nn & 63;
                        size_t dst = (((size_t)(bb * H_ + hh) * DK_ + dd) * T_ + ss);
                        __nv_bfloat16 hv, lv;
                        split_hl(e ? v1 : v0, hv, lv);
                        Ch[dst] = hv; Cl[dst] = lv;
                    }
                }
            }
        }
    }
}

// =====================================================================
// Fused flash attention with rel-shift:
//  S[t,s] = qu·k[s] + qv·p[T-1-t+s]  (qu,qv pre-scaled by 1/8)
//  online softmax + masked, O = attn @ V.  bf16x3 precision everywhere.
// Block: 128 t-rows (8 warps x 16), s-tiles of 64, grid (8, B*H).
// =====================================================================
#define FL_SMEM 137472

__global__ void __launch_bounds__(256) flash_kernel(
    const float* __restrict__ pu, const float* __restrict__ pv,
    const int* __restrict__ mask)
{
    extern __shared__ char sm[];
    __nv_bfloat16* KH = (__nv_bfloat16*)(sm);            // [64][72]
    __nv_bfloat16* KL = (__nv_bfloat16*)(sm + 9216);
    __nv_bfloat16* VH = (__nv_bfloat16*)(sm + 18432);    // [64 d][72 s]
    __nv_bfloat16* VL = (__nv_bfloat16*)(sm + 27648);
    __nv_bfloat16* PH = (__nv_bfloat16*)(sm + 36864);    // [192][72]
    __nv_bfloat16* PL = (__nv_bfloat16*)(sm + 64512);
    float* GS  = (float*)(sm + 92160);                   // [8 warps][16][88]
    float* MSK = (float*)(sm + 137216);                  // [64]
    // phase-0 aliases (dead after fragment load)
    __nv_bfloat16* QUH = (__nv_bfloat16*)(sm);           // [128][72]
    __nv_bfloat16* QUL = (__nv_bfloat16*)(sm + 18432);
    __nv_bfloat16* QVH = (__nv_bfloat16*)(sm + 36864);
    __nv_bfloat16* QVL = (__nv_bfloat16*)(sm + 55296);

    const int tid = threadIdx.x, lane = tid & 31, warp = tid >> 5;
    const int gid = lane >> 2, tig = lane & 3;
    const int bh = blockIdx.y, b = bh >> 3, h = bh & 7;
    const int t0 = blockIdx.x * 128;

    // ---- phase 0: qu/qv hi-lo staging (scaled by 1/sqrt(DK)=0.125) ----
    for (int x = tid; x < 2048; x += 256) {
        int r = x >> 4, c = (x & 15) << 2;
        float4 q4 = *(const float4*)(g_Q + ((size_t)(b * T_ + t0 + r)) * F_ + h * DK_ + c);
        float4 u4 = *(const float4*)(pu + h * DK_ + c);
        float4 v4 = *(const float4*)(pv + h * DK_ + c);
        float qs[4] = {q4.x, q4.y, q4.z, q4.w};
        float us[4] = {u4.x, u4.y, u4.z, u4.w};
        float vs[4] = {v4.x, v4.y, v4.z, v4.w};
#pragma unroll
        for (int e = 0; e < 4; e++) {
            __nv_bfloat16 hh, ll;
            split_hl((qs[e] + us[e]) * 0.125f, hh, ll);
            QUH[r * 72 + c + e] = hh; QUL[r * 72 + c + e] = ll;
            split_hl((qs[e] + vs[e]) * 0.125f, hh, ll);
            QVH[r * 72 + c + e] = hh; QVL[r * 72 + c + e] = ll;
        }
    }
    __syncthreads();

    unsigned quh[4][4], qul[4][4], qvh[4][4], qvl[4][4];
    {
        int ar = warp * 16 + (lane & 15);
        int ac = (lane >> 4) << 3;
#pragma unroll
        for (int kc = 0; kc < 4; kc++) {
            ldsm_x4(smem_u32(&QUH[ar * 72 + kc * 16 + ac]), quh[kc][0], quh[kc][1], quh[kc][2], quh[kc][3]);
            ldsm_x4(smem_u32(&QUL[ar * 72 + kc * 16 + ac]), qul[kc][0], qul[kc][1], qul[kc][2], qul[kc][3]);
            ldsm_x4(smem_u32(&QVH[ar * 72 + kc * 16 + ac]), qvh[kc][0], qvh[kc][1], qvh[kc][2], qvh[kc][3]);
            ldsm_x4(smem_u32(&QVL[ar * 72 + kc * 16 + ac]), qvl[kc][0], qvl[kc][1], qvl[kc][2], qvl[kc][3]);
        }
    }
    __syncthreads();

    float o[8][4];
#pragma unroll
    for (int nt = 0; nt < 8; nt++)
#pragma unroll
        for (int q = 0; q < 4; q++) o[nt][q] = 0.f;
    float mr0 = -1e30f, mr1 = -1e30f, l0 = 0.f, l1 = 0.f;
    float* GSw = GS + warp * (16 * 88);

    for (int s0 = 0; s0 < T_; s0 += 64) {
        const int c0 = T_ - 1 - t0 + s0;
        const int pbase = c0 - 127;

        // ---- stage K, V^T (8 bf16 per uint4) ----
        for (int x = tid; x < 512; x += 256) {
            int r = x >> 3, c = (x & 7) << 3;
            size_t ksrc = ((size_t)(b * T_ + s0 + r)) * F_ + h * DK_ + c;
            *(uint4*)&KH[r * 72 + c] = *(const uint4*)(g_Kh + ksrc);
            *(uint4*)&KL[r * 72 + c] = *(const uint4*)(g_Kl + ksrc);
            size_t vsrc = ((size_t)bh * DK_ + r) * T_ + s0 + c;
            *(uint4*)&VH[r * 72 + c] = *(const uint4*)(g_Vth + vsrc);
            *(uint4*)&VL[r * 72 + c] = *(const uint4*)(g_Vtl + vsrc);
        }
        // ---- stage P window: 192 rows ----
        for (int x = tid; x < 1536; x += 256) {
            int r = x >> 3, c = (x & 7) << 3;
            size_t psrc = ((size_t)(pbase + r)) * F_ + h * DK_ + c;
            *(uint4*)&PH[r * 72 + c] = *(const uint4*)(g_Ph + psrc);
            *(uint4*)&PL[r * 72 + c] = *(const uint4*)(g_Pl + psrc);
        }
        if (tid < 64) MSK[tid] = (mask[b * T_ + s0 + tid] == 0) ? -3.0e38f : 0.f;
        __syncthreads();

        // ---- G = qv_strip @ Pwin^T  (banded BD, 80 cols) ----
        {
            int prow = 112 - 16 * warp + (lane & 7);
            int psel = ((lane >> 3) & 1) << 3;
#pragma unroll
            for (int nt = 0; nt < 10; nt++) {
                float g0 = 0.f, g1 = 0.f, g2 = 0.f, g3 = 0.f;
#pragma unroll
                for (int kc = 0; kc < 4; kc++) {
                    unsigned p0, p1, q0, q1;
                    unsigned addr = smem_u32(&PH[(prow + nt * 8) * 72 + kc * 16 + psel]);
                    ldsm_x2(addr, p0, p1);
                    addr = smem_u32(&PL[(prow + nt * 8) * 72 + kc * 16 + psel]);
                    ldsm_x2(addr, q0, q1);
                    mma_bf16(g0, g1, g2, g3, qvh[kc][0], qvh[kc][1], qvh[kc][2], qvh[kc][3], p0, p1);
                    mma_bf16(g0, g1, g2, g3, qvh[kc][0], qvh[kc][1], qvh[kc][2], qvh[kc][3], q0, q1);
                    mma_bf16(g0, g1, g2, g3, qvl[kc][0], qvl[kc][1], qvl[kc][2], qvl[kc][3], p0, p1);
                }
                int gc = nt * 8 + 2 * tig;
                GSw[gid * 88 + gc] = g0;
                GSw[gid * 88 + gc + 1] = g1;
                GSw[(gid + 8) * 88 + gc] = g2;
                GSw[(gid + 8) * 88 + gc + 1] = g3;
            }
        }
        __syncwarp();

        // ---- S = qu @ K^T + band(G) + mask ----
        float sf[8][4];
        {
            int krow = lane & 7;
            int ksel = ((lane >> 3) & 1) << 3;
#pragma unroll
            for (int nt = 0; nt < 8; nt++) {
                float a0 = 0.f, a1 = 0.f, a2 = 0.f, a3 = 0.f;
#pragma unroll
                for (int kc = 0; kc < 4; kc++) {
                    unsigned k0, k1, k2, k3;
                    ldsm_x2(smem_u32(&KH[(nt * 8 + krow) * 72 + kc * 16 + ksel]), k0, k1);
                    ldsm_x2(smem_u32(&KL[(nt * 8 + krow) * 72 + kc * 16 + ksel]), k2, k3);
                    mma_bf16(a0, a1, a2, a3, quh[kc][0], quh[kc][1], quh[kc][2], quh[kc][3], k0, k1);
                    mma_bf16(a0, a1, a2, a3, quh[kc][0], quh[kc][1], quh[kc][2], quh[kc][3], k2, k3);
                    mma_bf16(a0, a1, a2, a3, qul[kc][0], qul[kc][1], qul[kc][2], qul[kc][3], k0, k1);
                }
                int col = nt * 8 + 2 * tig;
                sf[nt][0] = a0 + GSw[gid * 88 + col - gid + 15] + MSK[col];
                sf[nt][1] = a1 + GSw[gid * 88 + col - gid + 16] + MSK[col + 1];
                sf[nt][2] = a2 + GSw[(gid + 8) * 88 + col - gid + 7] + MSK[col];
                sf[nt][3] = a3 + GSw[(gid + 8) * 88 + col - gid + 8] + MSK[col + 1];
            }
        }

        // ---- online softmax (rows gid, gid+8 of this warp strip) ----
        float mx0 = -1e30f, mx1 = -1e30f;
#pragma unroll
        for (int nt = 0; nt < 8; nt++) {
            mx0 = fmaxf(mx0, fmaxf(sf[nt][0], sf[nt][1]));
            mx1 = fmaxf(mx1, fmaxf(sf[nt][2], sf[nt][3]));
        }
        mx0 = fmaxf(mx0, __shfl_xor_sync(0xffffffffu, mx0, 1));
        mx0 = fmaxf(mx0, __shfl_xor_sync(0xffffffffu, mx0, 2));
        mx1 = fmaxf(mx1, __shfl_xor_sync(0xffffffffu, mx1, 1));
        mx1 = fmaxf(mx1, __shfl_xor_sync(0xffffffffu, mx1, 2));
        float mn0 = fmaxf(mr0, mx0), mn1 = fmaxf(mr1, mx1);
        float sc0 = __expf(mr0 - mn0), sc1 = __expf(mr1 - mn1);
        float su0 = 0.f, su1 = 0.f;
#pragma unroll
        for (int nt = 0; nt < 8; nt++) {
            sf[nt][0] = __expf(sf[nt][0] - mn0);
            sf[nt][1] = __expf(sf[nt][1] - mn0);
            sf[nt][2] = __expf(sf[nt][2] - mn1);
            sf[nt][3] = __expf(sf[nt][3] - mn1);
            su0 += sf[nt][0] + sf[nt][1];
            su1 += sf[nt][2] + sf[nt][3];
        }
        su0 += __shfl_xor_sync(0xffffffffu, su0, 1);
        su0 += __shfl_xor_sync(0xffffffffu, su0, 2);
        su1 += __shfl_xor_sync(0xffffffffu, su1, 1);
        su1 += __shfl_xor_sync(0xffffffffu, su1, 2);
        l0 = l0 * sc0 + su0;
        l1 = l1 * sc1 + su1;
        mr0 = mn0; mr1 = mn1;
#pragma unroll
        for (int nt = 0; nt < 8; nt++) {
            o[nt][0] *= sc0; o[nt][1] *= sc0;
            o[nt][2] *= sc1; o[nt][3] *= sc1;
        }

        // ---- O += P @ V  (P fragments converted in-register) ----
        {
            int vrow = lane & 7;
            int vsel = ((lane >> 3) & 1) << 3;
#pragma unroll
            for (int kc = 0; kc < 4; kc++) {
                unsigned ah[4], al[4];
                pack_hl(sf[2 * kc][0], sf[2 * kc][1], ah[0], al[0]);
                pack_hl(sf[2 * kc][2], sf[2 * kc][3], ah[1], al[1]);
                pack_hl(sf[2 * kc + 1][0], sf[2 * kc + 1][1], ah[2], al[2]);
                pack_hl(sf[2 * kc + 1][2], sf[2 * kc + 1][3], ah[3], al[3]);
#pragma unroll
                for (int nt = 0; nt < 8; nt++) {
                    unsigned v0, v1, w0, w1;
                    ldsm_x2(smem_u32(&VH[(nt * 8 + vrow) * 72 + kc * 16 + vsel]), v0, v1);
                    ldsm_x2(smem_u32(&VL[(nt * 8 + vrow) * 72 + kc * 16 + vsel]), w0, w1);
                    mma_bf16(o[nt][0], o[nt][1], o[nt][2], o[nt][3],
                             ah[0], ah[1], ah[2], ah[3], v0, v1);
                    mma_bf16(o[nt][0], o[nt][1], o[nt][2], o[nt][3],
                             ah[0], ah[1], ah[2], ah[3], w0, w1);
                    mma_bf16(o[nt][0], o[nt][1], o[nt][2], o[nt][3],
                             al[0], al[1], al[2], al[3], v0, v1);
                }
            }
        }
        __syncthreads();
    }

    // ---- epilogue ----
    float inv0 = (l0 > 0.f) ? 1.f / l0 : 0.f;
    float inv1 = (l1 > 0.f) ? 1.f / l1 : 0.f;
    int row0 = t0 + warp * 16 + gid;
#pragma unroll
    for (int nt = 0; nt < 8; nt++) {
        int colg = h * DK_ + nt * 8 + 2 * tig;
        float2 w0 = make_float2(o[nt][0] * inv0, o[nt][1] * inv0);
        *(float2*)&g_ctx[((size_t)(b * T_ + row0)) * F_ + colg] = w0;
        float2 w1 = make_float2(o[nt][2] * inv1, o[nt][3] * inv1);
        *(float2*)&g_ctx[((size_t)(b * T_ + row0 + 8)) * F_ + colg] = w1;
    }
}

// =====================================================================
extern "C" void kernel_launch(void* const* d_in, const int* in_sizes, int n_in,
                              void* d_out, int out_size)
{
    const float* query   = (const float*)d_in[0];
    const float* key_in  = (const float*)d_in[1];
    const float* value   = (const float*)d_in[2];
    const float* pos_emb = (const float*)d_in[3];
    const int*   mask    = (const int*)d_in[4];
    const float* Wq = (const float*)d_in[5];
    const float* bq = (const float*)d_in[6];
    const float* Wk = (const float*)d_in[7];
    const float* bk = (const float*)d_in[8];
    const float* Wv = (const float*)d_in[9];
    const float* bv = (const float*)d_in[10];
    const float* Wo = (const float*)d_in[11];
    const float* bo = (const float*)d_in[12];
    const float* Wp = (const float*)d_in[13];
    const float* pu = (const float*)d_in[14];
    const float* pv = (const float*)d_in[15];
    float* out = (float*)d_out;

    float *Qp, *Cp;
    __nv_bfloat16 *Khp, *Klp, *Vthp, *Vtlp, *Php, *Plp;
    cudaGetSymbolAddress((void**)&Qp,   g_Q);
    cudaGetSymbolAddress((void**)&Cp,   g_ctx);
    cudaGetSymbolAddress((void**)&Khp,  g_Kh);
    cudaGetSymbolAddress((void**)&Klp,  g_Kl);
    cudaGetSymbolAddress((void**)&Vthp, g_Vth);
    cudaGetSymbolAddress((void**)&Vtlp, g_Vtl);
    cudaGetSymbolAddress((void**)&Php,  g_Ph);
    cudaGetSymbolAddress((void**)&Plp,  g_Pl);

    cudaFuncSetAttribute(flash_kernel, cudaFuncAttributeMaxDynamicSharedMemorySize, FL_SMEM);

    dim3 blk(256);

    // projections
    gemm_bf16x3<<<dim3(4, 64), blk>>>(query,  Wq, bq, Qp, nullptr, nullptr,
                                      B_ * T_, F_, F_, 0);
    gemm_bf16x3<<<dim3(4, 64), blk>>>(key_in, Wk, bk, nullptr, Khp, Klp,
                                      B_ * T_, F_, F_, 1);
    gemm_bf16x3<<<dim3(4, 64), blk>>>(value,  Wv, bv, nullptr, Vthp, Vtlp,
                                      B_ * T_, F_, F_, 2);
    gemm_bf16x3<<<dim3(4, 16), blk>>>(pos_emb, Wp, nullptr, nullptr, Php, Plp,
                                      P_, F_, F_, 1);

    // fused attention (scores + rel-shift + softmax + AV)
    flash_kernel<<<dim3(8, B_ * H_), blk, FL_SMEM>>>(pu, pv, mask);

    // output projection
    gemm_bf16x3<<<dim3(4, 64), blk>>>(Cp, Wo, bo, out, nullptr, nullptr,
                                      B_ * T_, F_, F_, 0);
}

// round 5
// speedup vs baseline: 2.8258x; 1.1175x over previous
#include <cuda_runtime.h>
#include <cuda_bf16.h>
#include <math.h>

#define B_ 8
#define T_ 1024
#define F_ 512
#define H_ 8
#define DK_ 64
#define P_ 2047

// -------- scratch (device globals; no allocations allowed) --------
__device__ float g_Q[(size_t)B_ * T_ * F_];                 // fp32 q proj
__device__ __nv_bfloat16 g_Kh[(size_t)B_ * T_ * F_];        // k hi
__device__ __nv_bfloat16 g_Kl[(size_t)B_ * T_ * F_];        // k lo
__device__ __nv_bfloat16 g_Vth[(size_t)B_ * H_ * DK_ * T_]; // v^T hi  [b,h,d,s]
__device__ __nv_bfloat16 g_Vtl[(size_t)B_ * H_ * DK_ * T_]; // v^T lo
__device__ __nv_bfloat16 g_Ph[(size_t)(P_ + 1) * F_];       // p hi (row 2047 spare)
__device__ __nv_bfloat16 g_Pl[(size_t)(P_ + 1) * F_];       // p lo
__device__ float g_ctx[(size_t)B_ * T_ * F_];

// =====================================================================
// Tensor-core helpers
// =====================================================================
__device__ __forceinline__ unsigned smem_u32(const void* p) {
    return (unsigned)__cvta_generic_to_shared(p);
}

__device__ __forceinline__ void ldsm_x4(unsigned addr, unsigned& r0, unsigned& r1,
                                        unsigned& r2, unsigned& r3) {
    asm volatile("ldmatrix.sync.aligned.m8n8.x4.shared.b16 {%0,%1,%2,%3}, [%4];"
                 : "=r"(r0), "=r"(r1), "=r"(r2), "=r"(r3) : "r"(addr));
}

__device__ __forceinline__ void ldsm_x2(unsigned addr, unsigned& r0, unsigned& r1) {
    asm volatile("ldmatrix.sync.aligned.m8n8.x2.shared.b16 {%0,%1}, [%2];"
                 : "=r"(r0), "=r"(r1) : "r"(addr));
}

__device__ __forceinline__ void mma_bf16(float& c0, float& c1, float& c2, float& c3,
                                         unsigned a0, unsigned a1, unsigned a2, unsigned a3,
                                         unsigned b0, unsigned b1) {
    asm volatile(
        "mma.sync.aligned.m16n8k16.row.col.f32.bf16.bf16.f32 "
        "{%0,%1,%2,%3},{%4,%5,%6,%7},{%8,%9},{%0,%1,%2,%3};"
        : "+f"(c0), "+f"(c1), "+f"(c2), "+f"(c3)
        : "r"(a0), "r"(a1), "r"(a2), "r"(a3), "r"(b0), "r"(b1));
}

__device__ __forceinline__ void split_hl(float x, __nv_bfloat16& h, __nv_bfloat16& l) {
    h = __float2bfloat16(x);
    l = __float2bfloat16(x - __bfloat162float(h));
}

__device__ __forceinline__ void pack_hl(float x0, float x1, unsigned& hi, unsigned& lo) {
    __nv_bfloat16 h0, l0, h1, l1;
    split_hl(x0, h0, l0);
    split_hl(x1, h1, l1);
    hi = ((unsigned)__bfloat16_as_ushort(h1) << 16) | (unsigned)__bfloat16_as_ushort(h0);
    lo = ((unsigned)__bfloat16_as_ushort(l1) << 16) | (unsigned)__bfloat16_as_ushort(l0);
}

__device__ __forceinline__ void cvt4(__nv_bfloat16* dh, __nv_bfloat16* dl, float4 v) {
    float f[4] = {v.x, v.y, v.z, v.w};
#pragma unroll
    for (int i = 0; i < 4; i++) split_hl(f[i], dh[i], dl[i]);
}

// =====================================================================
// bf16x3 tensor-core NT GEMM, multi-job batched over grid.z.
// C = A[M,512] @ W[512,512]^T (+bias); N=K=512 fixed.
// mode 0: fp32 -> C.  mode 1: bf16 hi/lo -> (Ch,Cl).
// mode 2: bf16 hi/lo transposed per-head: dst[((b*H+h)*64+d)*T + s]
// =====================================================================
#define BK_ 32
#define LDSA (BK_ + 8)
#define GN_ 512
#define GK_ 512

struct GemmJob {
    const float* A; const float* W; const float* bias;
    float* C; __nv_bfloat16* Ch; __nv_bfloat16* Cl;
    int M; int mode;
};
struct GemmJobs { GemmJob j[4]; };

__global__ void __launch_bounds__(256) gemm_multi(GemmJobs jobs)
{
    __shared__ __nv_bfloat16 Ah[128][LDSA], Al[128][LDSA];
    __shared__ __nv_bfloat16 Wh[128][LDSA], Wl[128][LDSA];

    const GemmJob job = jobs.j[blockIdx.z];
    const int M = job.M;
    const int m0 = blockIdx.y * 128;
    if (m0 >= M) return;
    const int n0 = blockIdx.x * 128;

    const float* __restrict__ A = job.A;
    const float* __restrict__ W = job.W;

    const int tid = threadIdx.x;
    const int lane = tid & 31;
    const int warp = tid >> 5;
    const int wm = warp & 1;
    const int wn = warp >> 1;

    const int arow = lane & 15;
    const int asel = (lane >> 4) << 3;
    const int bn_off = lane & 7;
    const int bsel = ((lane >> 3) & 1) << 3;

    float acc[4][4][4];
#pragma unroll
    for (int i = 0; i < 4; i++)
#pragma unroll
        for (int j = 0; j < 4; j++)
#pragma unroll
            for (int q = 0; q < 4; q++) acc[i][j][q] = 0.f;

    for (int k0 = 0; k0 < GK_; k0 += BK_) {
#pragma unroll
        for (int q = 0; q < 4; q++) {
            int idx = tid + q * 256;
            int row = idx >> 3;
            int col = (idx & 7) << 2;
            int gm = m0 + row; if (gm >= M) gm = M - 1;
            float4 a4 = *(const float4*)(A + (size_t)gm * GK_ + k0 + col);
            cvt4(&Ah[row][col], &Al[row][col], a4);
            int gn = n0 + row;
            float4 w4 = *(const float4*)(W + (size_t)gn * GK_ + k0 + col);
            cvt4(&Wh[row][col], &Wl[row][col], w4);
        }
        __syncthreads();

#pragma unroll
        for (int kk = 0; kk < 2; kk++) {
            const int kb = kk << 4;
            unsigned ah[4][4], al[4][4], bh[4][2], bl[4][2];
#pragma unroll
            for (int i = 0; i < 4; i++) {
                int r = wm * 64 + i * 16 + arow;
                ldsm_x4(smem_u32(&Ah[r][kb + asel]), ah[i][0], ah[i][1], ah[i][2], ah[i][3]);
                ldsm_x4(smem_u32(&Al[r][kb + asel]), al[i][0], al[i][1], al[i][2], al[i][3]);
            }
#pragma unroll
            for (int j = 0; j < 4; j++) {
                int n = wn * 32 + j * 8 + bn_off;
                ldsm_x2(smem_u32(&Wh[n][kb + bsel]), bh[j][0], bh[j][1]);
                ldsm_x2(smem_u32(&Wl[n][kb + bsel]), bl[j][0], bl[j][1]);
            }
#pragma unroll
            for (int i = 0; i < 4; i++)
#pragma unroll
                for (int j = 0; j < 4; j++) {
                    mma_bf16(acc[i][j][0], acc[i][j][1], acc[i][j][2], acc[i][j][3],
                             ah[i][0], ah[i][1], ah[i][2], ah[i][3], bh[j][0], bh[j][1]);
                    mma_bf16(acc[i][j][0], acc[i][j][1], acc[i][j][2], acc[i][j][3],
                             ah[i][0], ah[i][1], ah[i][2], ah[i][3], bl[j][0], bl[j][1]);
                    mma_bf16(acc[i][j][0], acc[i][j][1], acc[i][j][2], acc[i][j][3],
                             al[i][0], al[i][1], al[i][2], al[i][3], bh[j][0], bh[j][1]);
                }
        }
        __syncthreads();
    }

#pragma unroll
    for (int i = 0; i < 4; i++) {
        int mbase = m0 + wm * 64 + i * 16 + (lane >> 2);
#pragma unroll
        for (int j = 0; j < 4; j++) {
            int n = n0 + wn * 32 + j * 8 + (lane & 3) * 2;
            float bb0 = job.bias ? job.bias[n] : 0.f;
            float bb1 = job.bias ? job.bias[n + 1] : 0.f;
#pragma unroll
            for (int half = 0; half < 2; half++) {
                int m = mbase + half * 8;
                if (m >= M) continue;
                float v0 = acc[i][j][half * 2 + 0] + bb0;
                float v1 = acc[i][j][half * 2 + 1] + bb1;
                if (job.mode == 0) {
                    job.C[(size_t)m * GN_ + n] = v0;
                    job.C[(size_t)m * GN_ + n + 1] = v1;
                } else if (job.mode == 1) {
                    __nv_bfloat16 h0, l0, h1, l1;
                    split_hl(v0, h0, l0); split_hl(v1, h1, l1);
                    job.Ch[(size_t)m * GN_ + n] = h0; job.Cl[(size_t)m * GN_ + n] = l0;
                    job.Ch[(size_t)m * GN_ + n + 1] = h1; job.Cl[(size_t)m * GN_ + n + 1] = l1;
                } else {
                    int bb = m >> 10, ss = m & 1023;
#pragma unroll
                    for (int e = 0; e < 2; e++) {
                        int nn = n + e;
                        int hh = nn >> 6, dd = nn & 63;
                        size_t dst = (((size_t)(bb * H_ + hh) * DK_ + dd) * T_ + ss);
                        __nv_bfloat16 hv, lv;
                        split_hl(e ? v1 : v0, hv, lv);
                        job.Ch[dst] = hv; job.Cl[dst] = lv;
                    }
                }
            }
        }
    }
}

// =====================================================================
// Fused flash attention with rel-shift. 64 t-rows per block (4 warps),
// s-tiles of 64, grid (16, B*H). 96.5KB smem -> 2 CTAs/SM.
//  S[t,s] = qu·k[s] + qv·p[T-1-t+s]  (qu,qv pre-scaled by 1/8)
// =====================================================================
#define FL_SMEM 96512

__global__ void __launch_bounds__(128) flash_kernel(
    const float* __restrict__ pu, const float* __restrict__ pv,
    const int* __restrict__ mask)
{
    extern __shared__ char sm[];
    __nv_bfloat16* KH = (__nv_bfloat16*)(sm);            // [64][72]
    __nv_bfloat16* KL = (__nv_bfloat16*)(sm + 9216);
    __nv_bfloat16* VH = (__nv_bfloat16*)(sm + 18432);    // [64 d][72 s]
    __nv_bfloat16* VL = (__nv_bfloat16*)(sm + 27648);
    __nv_bfloat16* PH = (__nv_bfloat16*)(sm + 36864);    // [128][72]
    __nv_bfloat16* PL = (__nv_bfloat16*)(sm + 55296);
    float* GS  = (float*)(sm + 73728);                   // [4 warps][16][88]
    float* MSK = (float*)(sm + 96256);                   // [64]
    // phase-0 aliases (dead after fragment load)
    __nv_bfloat16* QUH = (__nv_bfloat16*)(sm);           // [64][72]
    __nv_bfloat16* QUL = (__nv_bfloat16*)(sm + 9216);
    __nv_bfloat16* QVH = (__nv_bfloat16*)(sm + 18432);
    __nv_bfloat16* QVL = (__nv_bfloat16*)(sm + 27648);

    const int tid = threadIdx.x, lane = tid & 31, warp = tid >> 5;
    const int gid = lane >> 2, tig = lane & 3;
    const int bh = blockIdx.y, b = bh >> 3, h = bh & 7;
    const int t0 = blockIdx.x * 64;

    // ---- phase 0: qu/qv hi-lo staging (scaled by 1/sqrt(DK)=0.125) ----
    for (int x = tid; x < 1024; x += 128) {
        int r = x >> 4, c = (x & 15) << 2;
        float4 q4 = *(const float4*)(g_Q + ((size_t)(b * T_ + t0 + r)) * F_ + h * DK_ + c);
        float4 u4 = *(const float4*)(pu + h * DK_ + c);
        float4 v4 = *(const float4*)(pv + h * DK_ + c);
        float qs[4] = {q4.x, q4.y, q4.z, q4.w};
        float us[4] = {u4.x, u4.y, u4.z, u4.w};
        float vs[4] = {v4.x, v4.y, v4.z, v4.w};
#pragma unroll
        for (int e = 0; e < 4; e++) {
            __nv_bfloat16 hh, ll;
            split_hl((qs[e] + us[e]) * 0.125f, hh, ll);
            QUH[r * 72 + c + e] = hh; QUL[r * 72 + c + e] = ll;
            split_hl((qs[e] + vs[e]) * 0.125f, hh, ll);
            QVH[r * 72 + c + e] = hh; QVL[r * 72 + c + e] = ll;
        }
    }
    __syncthreads();

    unsigned quh[4][4], qul[4][4], qvh[4][4], qvl[4][4];
    {
        int ar = warp * 16 + (lane & 15);
        int ac = (lane >> 4) << 3;
#pragma unroll
        for (int kc = 0; kc < 4; kc++) {
            ldsm_x4(smem_u32(&QUH[ar * 72 + kc * 16 + ac]), quh[kc][0], quh[kc][1], quh[kc][2], quh[kc][3]);
            ldsm_x4(smem_u32(&QUL[ar * 72 + kc * 16 + ac]), qul[kc][0], qul[kc][1], qul[kc][2], qul[kc][3]);
            ldsm_x4(smem_u32(&QVH[ar * 72 + kc * 16 + ac]), qvh[kc][0], qvh[kc][1], qvh[kc][2], qvh[kc][3]);
            ldsm_x4(smem_u32(&QVL[ar * 72 + kc * 16 + ac]), qvl[kc][0], qvl[kc][1], qvl[kc][2], qvl[kc][3]);
        }
    }
    __syncthreads();

    float o[8][4];
#pragma unroll
    for (int nt = 0; nt < 8; nt++)
#pragma unroll
        for (int q = 0; q < 4; q++) o[nt][q] = 0.f;
    float mr0 = -1e30f, mr1 = -1e30f, l0 = 0.f, l1 = 0.f;
    float* GSw = GS + warp * (16 * 88);

    for (int s0 = 0; s0 < T_; s0 += 64) {
        const int c0 = T_ - 1 - t0 + s0;
        const int pbase = c0 - 63;

        // ---- stage K, V^T ----
        for (int x = tid; x < 512; x += 128) {
            int r = x >> 3, c = (x & 7) << 3;
            size_t ksrc = ((size_t)(b * T_ + s0 + r)) * F_ + h * DK_ + c;
            *(uint4*)&KH[r * 72 + c] = *(const uint4*)(g_Kh + ksrc);
            *(uint4*)&KL[r * 72 + c] = *(const uint4*)(g_Kl + ksrc);
            size_t vsrc = ((size_t)bh * DK_ + r) * T_ + s0 + c;
            *(uint4*)&VH[r * 72 + c] = *(const uint4*)(g_Vth + vsrc);
            *(uint4*)&VL[r * 72 + c] = *(const uint4*)(g_Vtl + vsrc);
        }
        // ---- stage P window: 128 rows ----
        for (int x = tid; x < 1024; x += 128) {
            int r = x >> 3, c = (x & 7) << 3;
            size_t psrc = ((size_t)(pbase + r)) * F_ + h * DK_ + c;
            *(uint4*)&PH[r * 72 + c] = *(const uint4*)(g_Ph + psrc);
            *(uint4*)&PL[r * 72 + c] = *(const uint4*)(g_Pl + psrc);
        }
        if (tid < 64) MSK[tid] = (mask[b * T_ + s0 + tid] == 0) ? -3.0e38f : 0.f;
        __syncthreads();

        // ---- G = qv_strip @ Pwin^T  (banded BD, 80 cols) ----
        {
            int prow = 48 - 16 * warp + (lane & 7);
            int psel = ((lane >> 3) & 1) << 3;
#pragma unroll
            for (int nt = 0; nt < 10; nt++) {
                float g0 = 0.f, g1 = 0.f, g2 = 0.f, g3 = 0.f;
#pragma unroll
                for (int kc = 0; kc < 4; kc++) {
                    unsigned p0, p1, q0, q1;
                    unsigned addr = smem_u32(&PH[(prow + nt * 8) * 72 + kc * 16 + psel]);
                    ldsm_x2(addr, p0, p1);
                    addr = smem_u32(&PL[(prow + nt * 8) * 72 + kc * 16 + psel]);
                    ldsm_x2(addr, q0, q1);
                    mma_bf16(g0, g1, g2, g3, qvh[kc][0], qvh[kc][1], qvh[kc][2], qvh[kc][3], p0, p1);
                    mma_bf16(g0, g1, g2, g3, qvh[kc][0], qvh[kc][1], qvh[kc][2], qvh[kc][3], q0, q1);
                    mma_bf16(g0, g1, g2, g3, qvl[kc][0], qvl[kc][1], qvl[kc][2], qvl[kc][3], p0, p1);
                }
                int gc = nt * 8 + 2 * tig;
                GSw[gid * 88 + gc] = g0;
                GSw[gid * 88 + gc + 1] = g1;
                GSw[(gid + 8) * 88 + gc] = g2;
                GSw[(gid + 8) * 88 + gc + 1] = g3;
            }
        }
        __syncwarp();

        // ---- S = qu @ K^T + band(G) + mask ----
        float sf[8][4];
        {
            int krow = lane & 7;
            int ksel = ((lane >> 3) & 1) << 3;
#pragma unroll
            for (int nt = 0; nt < 8; nt++) {
                float a0 = 0.f, a1 = 0.f, a2 = 0.f, a3 = 0.f;
#pragma unroll
                for (int kc = 0; kc < 4; kc++) {
                    unsigned k0, k1, k2, k3;
                    ldsm_x2(smem_u32(&KH[(nt * 8 + krow) * 72 + kc * 16 + ksel]), k0, k1);
                    ldsm_x2(smem_u32(&KL[(nt * 8 + krow) * 72 + kc * 16 + ksel]), k2, k3);
                    mma_bf16(a0, a1, a2, a3, quh[kc][0], quh[kc][1], quh[kc][2], quh[kc][3], k0, k1);
                    mma_bf16(a0, a1, a2, a3, quh[kc][0], quh[kc][1], quh[kc][2], quh[kc][3], k2, k3);
                    mma_bf16(a0, a1, a2, a3, qul[kc][0], qul[kc][1], qul[kc][2], qul[kc][3], k0, k1);
                }
                int col = nt * 8 + 2 * tig;
                sf[nt][0] = a0 + GSw[gid * 88 + col - gid + 15] + MSK[col];
                sf[nt][1] = a1 + GSw[gid * 88 + col - gid + 16] + MSK[col + 1];
                sf[nt][2] = a2 + GSw[(gid + 8) * 88 + col - gid + 7] + MSK[col];
                sf[nt][3] = a3 + GSw[(gid + 8) * 88 + col - gid + 8] + MSK[col + 1];
            }
        }

        // ---- online softmax ----
        float mx0 = -1e30f, mx1 = -1e30f;
#pragma unroll
        for (int nt = 0; nt < 8; nt++) {
            mx0 = fmaxf(mx0, fmaxf(sf[nt][0], sf[nt][1]));
            mx1 = fmaxf(mx1, fmaxf(sf[nt][2], sf[nt][3]));
        }
        mx0 = fmaxf(mx0, __shfl_xor_sync(0xffffffffu, mx0, 1));
        mx0 = fmaxf(mx0, __shfl_xor_sync(0xffffffffu, mx0, 2));
        mx1 = fmaxf(mx1, __shfl_xor_sync(0xffffffffu, mx1, 1));
        mx1 = fmaxf(mx1, __shfl_xor_sync(0xffffffffu, mx1, 2));
        float mn0 = fmaxf(mr0, mx0), mn1 = fmaxf(mr1, mx1);
        float sc0 = __expf(mr0 - mn0), sc1 = __expf(mr1 - mn1);
        float su0 = 0.f, su1 = 0.f;
#pragma unroll
        for (int nt = 0; nt < 8; nt++) {
            sf[nt][0] = __expf(sf[nt][0] - mn0);
            sf[nt][1] = __expf(sf[nt][1] - mn0);
            sf[nt][2] = __expf(sf[nt][2] - mn1);
            sf[nt][3] = __expf(sf[nt][3] - mn1);
            su0 += sf[nt][0] + sf[nt][1];
            su1 += sf[nt][2] + sf[nt][3];
        }
        su0 += __shfl_xor_sync(0xffffffffu, su0, 1);
        su0 += __shfl_xor_sync(0xffffffffu, su0, 2);
        su1 += __shfl_xor_sync(0xffffffffu, su1, 1);
        su1 += __shfl_xor_sync(0xffffffffu, su1, 2);
        l0 = l0 * sc0 + su0;
        l1 = l1 * sc1 + su1;
        mr0 = mn0; mr1 = mn1;
#pragma unroll
        for (int nt = 0; nt < 8; nt++) {
            o[nt][0] *= sc0; o[nt][1] *= sc0;
            o[nt][2] *= sc1; o[nt][3] *= sc1;
        }

        // ---- O += P @ V ----
        {
            int vrow = lane & 7;
            int vsel = ((lane >> 3) & 1) << 3;
#pragma unroll
            for (int kc = 0; kc < 4; kc++) {
                unsigned ah[4], al[4];
                pack_hl(sf[2 * kc][0], sf[2 * kc][1], ah[0], al[0]);
                pack_hl(sf[2 * kc][2], sf[2 * kc][3], ah[1], al[1]);
                pack_hl(sf[2 * kc + 1][0], sf[2 * kc + 1][1], ah[2], al[2]);
                pack_hl(sf[2 * kc + 1][2], sf[2 * kc + 1][3], ah[3], al[3]);
#pragma unroll
                for (int nt = 0; nt < 8; nt++) {
                    unsigned v0, v1, w0, w1;
                    ldsm_x2(smem_u32(&VH[(nt * 8 + vrow) * 72 + kc * 16 + vsel]), v0, v1);
                    ldsm_x2(smem_u32(&VL[(nt * 8 + vrow) * 72 + kc * 16 + vsel]), w0, w1);
                    mma_bf16(o[nt][0], o[nt][1], o[nt][2], o[nt][3],
                             ah[0], ah[1], ah[2], ah[3], v0, v1);
                    mma_bf16(o[nt][0], o[nt][1], o[nt][2], o[nt][3],
                             ah[0], ah[1], ah[2], ah[3], w0, w1);
                    mma_bf16(o[nt][0], o[nt][1], o[nt][2], o[nt][3],
                             al[0], al[1], al[2], al[3], v0, v1);
                }
            }
        }
        __syncthreads();
    }

    // ---- epilogue ----
    float inv0 = (l0 > 0.f) ? 1.f / l0 : 0.f;
    float inv1 = (l1 > 0.f) ? 1.f / l1 : 0.f;
    int row0 = t0 + warp * 16 + gid;
#pragma unroll
    for (int nt = 0; nt < 8; nt++) {
        int colg = h * DK_ + nt * 8 + 2 * tig;
        float2 w0 = make_float2(o[nt][0] * inv0, o[nt][1] * inv0);
        *(float2*)&g_ctx[((size_t)(b * T_ + row0)) * F_ + colg] = w0;
        float2 w1 = make_float2(o[nt][2] * inv1, o[nt][3] * inv1);
        *(float2*)&g_ctx[((size_t)(b * T_ + row0 + 8)) * F_ + colg] = w1;
    }
}

// =====================================================================
extern "C" void kernel_launch(void* const* d_in, const int* in_sizes, int n_in,
                              void* d_out, int out_size)
{
    const float* query   = (const float*)d_in[0];
    const float* key_in  = (const float*)d_in[1];
    const float* value   = (const float*)d_in[2];
    const float* pos_emb = (const float*)d_in[3];
    const int*   mask    = (const int*)d_in[4];
    const float* Wq = (const float*)d_in[5];
    const float* bq = (const float*)d_in[6];
    const float* Wk = (const float*)d_in[7];
    const float* bk = (const float*)d_in[8];
    const float* Wv = (const float*)d_in[9];
    const float* bv = (const float*)d_in[10];
    const float* Wo = (const float*)d_in[11];
    const float* bo = (const float*)d_in[12];
    const float* Wp = (const float*)d_in[13];
    const float* pu = (const float*)d_in[14];
    const float* pv = (const float*)d_in[15];
    float* out = (float*)d_out;

    float *Qp, *Cp;
    __nv_bfloat16 *Khp, *Klp, *Vthp, *Vtlp, *Php, *Plp;
    cudaGetSymbolAddress((void**)&Qp,   g_Q);
    cudaGetSymbolAddress((void**)&Cp,   g_ctx);
    cudaGetSymbolAddress((void**)&Khp,  g_Kh);
    cudaGetSymbolAddress((void**)&Klp,  g_Kl);
    cudaGetSymbolAddress((void**)&Vthp, g_Vth);
    cudaGetSymbolAddress((void**)&Vtlp, g_Vtl);
    cudaGetSymbolAddress((void**)&Php,  g_Ph);
    cudaGetSymbolAddress((void**)&Plp,  g_Pl);

    cudaFuncSetAttribute(flash_kernel, cudaFuncAttributeMaxDynamicSharedMemorySize, FL_SMEM);

    // ---- all 4 input projections in ONE launch (grid.z = job id) ----
    GemmJobs pj;
    pj.j[0] = { query,   Wq, bq,      Qp,      nullptr, nullptr, B_ * T_, 0 };
    pj.j[1] = { key_in,  Wk, bk,      nullptr, Khp,     Klp,     B_ * T_, 1 };
    pj.j[2] = { value,   Wv, bv,      nullptr, Vthp,    Vtlp,    B_ * T_, 2 };
    pj.j[3] = { pos_emb, Wp, nullptr, nullptr, Php,     Plp,     P_,      1 };
    gemm_multi<<<dim3(4, 64, 4), 256>>>(pj);

    // fused attention (scores + rel-shift + softmax + AV)
    flash_kernel<<<dim3(16, B_ * H_), 128, FL_SMEM>>>(pu, pv, mask);

    // output projection
    GemmJobs oj;
    oj.j[0] = { Cp, Wo, bo, out, nullptr, nullptr, B_ * T_, 0 };
    oj.j[1] = oj.j[0]; oj.j[2] = oj.j[0]; oj.j[3] = oj.j[0];
    gemm_multi<<<dim3(4, 64, 1), 256>>>(oj);
}

// round 6
// speedup vs baseline: 3.1090x; 1.1002x over previous
#include <cuda_runtime.h>
#include <cuda_bf16.h>
#include <math.h>

#define B_ 8
#define T_ 1024
#define F_ 512
#define H_ 8
#define DK_ 64
#define P_ 2047

// -------- scratch (device globals; no allocations allowed) --------
__device__ float g_Q[(size_t)B_ * T_ * F_];                 // fp32 q proj
__device__ __nv_bfloat16 g_Kh[(size_t)B_ * T_ * F_];        // k hi
__device__ __nv_bfloat16 g_Kl[(size_t)B_ * T_ * F_];        // k lo
__device__ __nv_bfloat16 g_Vth[(size_t)B_ * H_ * DK_ * T_]; // v^T hi  [b,h,d,s]
__device__ __nv_bfloat16 g_Vtl[(size_t)B_ * H_ * DK_ * T_]; // v^T lo
__device__ __nv_bfloat16 g_Ph[(size_t)(P_ + 1) * F_];       // p hi (row 2047 spare)
__device__ __nv_bfloat16 g_Pl[(size_t)(P_ + 1) * F_];       // p lo
__device__ float g_ctx[(size_t)B_ * T_ * F_];

// =====================================================================
// Tensor-core helpers
// =====================================================================
__device__ __forceinline__ unsigned smem_u32(const void* p) {
    return (unsigned)__cvta_generic_to_shared(p);
}

__device__ __forceinline__ void ldsm_x4(unsigned addr, unsigned& r0, unsigned& r1,
                                        unsigned& r2, unsigned& r3) {
    asm volatile("ldmatrix.sync.aligned.m8n8.x4.shared.b16 {%0,%1,%2,%3}, [%4];"
                 : "=r"(r0), "=r"(r1), "=r"(r2), "=r"(r3) : "r"(addr));
}

__device__ __forceinline__ void ldsm_x2(unsigned addr, unsigned& r0, unsigned& r1) {
    asm volatile("ldmatrix.sync.aligned.m8n8.x2.shared.b16 {%0,%1}, [%2];"
                 : "=r"(r0), "=r"(r1) : "r"(addr));
}

__device__ __forceinline__ void mma_bf16(float& c0, float& c1, float& c2, float& c3,
                                         unsigned a0, unsigned a1, unsigned a2, unsigned a3,
                                         unsigned b0, unsigned b1) {
    asm volatile(
        "mma.sync.aligned.m16n8k16.row.col.f32.bf16.bf16.f32 "
        "{%0,%1,%2,%3},{%4,%5,%6,%7},{%8,%9},{%0,%1,%2,%3};"
        : "+f"(c0), "+f"(c1), "+f"(c2), "+f"(c3)
        : "r"(a0), "r"(a1), "r"(a2), "r"(a3), "r"(b0), "r"(b1));
}

__device__ __forceinline__ void split_hl(float x, __nv_bfloat16& h, __nv_bfloat16& l) {
    h = __float2bfloat16(x);
    l = __float2bfloat16(x - __bfloat162float(h));
}

__device__ __forceinline__ void pack_hl(float x0, float x1, unsigned& hi, unsigned& lo) {
    __nv_bfloat16 h0, l0, h1, l1;
    split_hl(x0, h0, l0);
    split_hl(x1, h1, l1);
    hi = ((unsigned)__bfloat16_as_ushort(h1) << 16) | (unsigned)__bfloat16_as_ushort(h0);
    lo = ((unsigned)__bfloat16_as_ushort(l1) << 16) | (unsigned)__bfloat16_as_ushort(l0);
}

__device__ __forceinline__ void cvt4(__nv_bfloat16* dh, __nv_bfloat16* dl, float4 v) {
    float f[4] = {v.x, v.y, v.z, v.w};
#pragma unroll
    for (int i = 0; i < 4; i++) split_hl(f[i], dh[i], dl[i]);
}

__device__ __forceinline__ void cp16(void* smem_dst, const void* gsrc) {
    unsigned d = smem_u32(smem_dst);
    asm volatile("cp.async.cg.shared.global [%0], [%1], 16;" :: "r"(d), "l"(gsrc));
}

// =====================================================================
// bf16x3 tensor-core NT GEMM, multi-job batched over grid.z. (unchanged)
// =====================================================================
#define BK_ 32
#define LDSA (BK_ + 8)
#define GN_ 512
#define GK_ 512

struct GemmJob {
    const float* A; const float* W; const float* bias;
    float* C; __nv_bfloat16* Ch; __nv_bfloat16* Cl;
    int M; int mode;
};
struct GemmJobs { GemmJob j[4]; };

__global__ void __launch_bounds__(256) gemm_multi(GemmJobs jobs)
{
    __shared__ __nv_bfloat16 Ah[128][LDSA], Al[128][LDSA];
    __shared__ __nv_bfloat16 Wh[128][LDSA], Wl[128][LDSA];

    const GemmJob job = jobs.j[blockIdx.z];
    const int M = job.M;
    const int m0 = blockIdx.y * 128;
    if (m0 >= M) return;
    const int n0 = blockIdx.x * 128;

    const float* __restrict__ A = job.A;
    const float* __restrict__ W = job.W;

    const int tid = threadIdx.x;
    const int lane = tid & 31;
    const int warp = tid >> 5;
    const int wm = warp & 1;
    const int wn = warp >> 1;

    const int arow = lane & 15;
    const int asel = (lane >> 4) << 3;
    const int bn_off = lane & 7;
    const int bsel = ((lane >> 3) & 1) << 3;

    float acc[4][4][4];
#pragma unroll
    for (int i = 0; i < 4; i++)
#pragma unroll
        for (int j = 0; j < 4; j++)
#pragma unroll
            for (int q = 0; q < 4; q++) acc[i][j][q] = 0.f;

    for (int k0 = 0; k0 < GK_; k0 += BK_) {
#pragma unroll
        for (int q = 0; q < 4; q++) {
            int idx = tid + q * 256;
            int row = idx >> 3;
            int col = (idx & 7) << 2;
            int gm = m0 + row; if (gm >= M) gm = M - 1;
            float4 a4 = *(const float4*)(A + (size_t)gm * GK_ + k0 + col);
            cvt4(&Ah[row][col], &Al[row][col], a4);
            int gn = n0 + row;
            float4 w4 = *(const float4*)(W + (size_t)gn * GK_ + k0 + col);
            cvt4(&Wh[row][col], &Wl[row][col], w4);
        }
        __syncthreads();

#pragma unroll
        for (int kk = 0; kk < 2; kk++) {
            const int kb = kk << 4;
            unsigned ah[4][4], al[4][4], bh[4][2], bl[4][2];
#pragma unroll
            for (int i = 0; i < 4; i++) {
                int r = wm * 64 + i * 16 + arow;
                ldsm_x4(smem_u32(&Ah[r][kb + asel]), ah[i][0], ah[i][1], ah[i][2], ah[i][3]);
                ldsm_x4(smem_u32(&Al[r][kb + asel]), al[i][0], al[i][1], al[i][2], al[i][3]);
            }
#pragma unroll
            for (int j = 0; j < 4; j++) {
                int n = wn * 32 + j * 8 + bn_off;
                ldsm_x2(smem_u32(&Wh[n][kb + bsel]), bh[j][0], bh[j][1]);
                ldsm_x2(smem_u32(&Wl[n][kb + bsel]), bl[j][0], bl[j][1]);
            }
#pragma unroll
            for (int i = 0; i < 4; i++)
#pragma unroll
                for (int j = 0; j < 4; j++) {
                    mma_bf16(acc[i][j][0], acc[i][j][1], acc[i][j][2], acc[i][j][3],
                             ah[i][0], ah[i][1], ah[i][2], ah[i][3], bh[j][0], bh[j][1]);
                    mma_bf16(acc[i][j][0], acc[i][j][1], acc[i][j][2], acc[i][j][3],
                             ah[i][0], ah[i][1], ah[i][2], ah[i][3], bl[j][0], bl[j][1]);
                    mma_bf16(acc[i][j][0], acc[i][j][1], acc[i][j][2], acc[i][j][3],
                             al[i][0], al[i][1], al[i][2], al[i][3], bh[j][0], bh[j][1]);
                }
        }
        __syncthreads();
    }

#pragma unroll
    for (int i = 0; i < 4; i++) {
        int mbase = m0 + wm * 64 + i * 16 + (lane >> 2);
#pragma unroll
        for (int j = 0; j < 4; j++) {
            int n = n0 + wn * 32 + j * 8 + (lane & 3) * 2;
            float bb0 = job.bias ? job.bias[n] : 0.f;
            float bb1 = job.bias ? job.bias[n + 1] : 0.f;
#pragma unroll
            for (int half = 0; half < 2; half++) {
                int m = mbase + half * 8;
                if (m >= M) continue;
                float v0 = acc[i][j][half * 2 + 0] + bb0;
                float v1 = acc[i][j][half * 2 + 1] + bb1;
                if (job.mode == 0) {
                    job.C[(size_t)m * GN_ + n] = v0;
                    job.C[(size_t)m * GN_ + n + 1] = v1;
                } else if (job.mode == 1) {
                    __nv_bfloat16 h0, l0, h1, l1;
                    split_hl(v0, h0, l0); split_hl(v1, h1, l1);
                    job.Ch[(size_t)m * GN_ + n] = h0; job.Cl[(size_t)m * GN_ + n] = l0;
                    job.Ch[(size_t)m * GN_ + n + 1] = h1; job.Cl[(size_t)m * GN_ + n + 1] = l1;
                } else {
                    int bb = m >> 10, ss = m & 1023;
#pragma unroll
                    for (int e = 0; e < 2; e++) {
                        int nn = n + e;
                        int hh = nn >> 6, dd = nn & 63;
                        size_t dst = (((size_t)(bb * H_ + hh) * DK_ + dd) * T_ + ss);
                        __nv_bfloat16 hv, lv;
                        split_hl(e ? v1 : v0, hv, lv);
                        job.Ch[dst] = hv; job.Cl[dst] = lv;
                    }
                }
            }
        }
    }
}

// =====================================================================
// Fused flash attention, software-pipelined with cp.async.
// 8 warps, 128 t-rows/block, grid (8, B*H). K/V double-buffered,
// P as a 256-row circular window (64 new rows per s-tile).
// =====================================================================
#define FL_SMEM 192768

__global__ void __launch_bounds__(256) flash_kernel(
    const float* __restrict__ pu, const float* __restrict__ pv,
    const int* __restrict__ mask)
{
    extern __shared__ char sm[];
    __nv_bfloat16* KH = (__nv_bfloat16*)(sm);             // 2 x [64][72]
    __nv_bfloat16* KL = (__nv_bfloat16*)(sm + 18432);
    __nv_bfloat16* VH = (__nv_bfloat16*)(sm + 36864);     // 2 x [64 d][72 s]
    __nv_bfloat16* VL = (__nv_bfloat16*)(sm + 55296);
    __nv_bfloat16* PH = (__nv_bfloat16*)(sm + 73728);     // [256][72] circular
    __nv_bfloat16* PL = (__nv_bfloat16*)(sm + 110592);
    float* GS  = (float*)(sm + 147456);                   // [8 warps][16][88]
    float* MSK = (float*)(sm + 192512);                   // [64]
    // prologue aliases over the P region (dead before first P prefetch)
    __nv_bfloat16* QUH = (__nv_bfloat16*)(sm + 73728);    // [128][72]
    __nv_bfloat16* QUL = (__nv_bfloat16*)(sm + 92160);
    __nv_bfloat16* QVH = (__nv_bfloat16*)(sm + 110592);
    __nv_bfloat16* QVL = (__nv_bfloat16*)(sm + 129024);

    const int tid = threadIdx.x, lane = tid & 31, warp = tid >> 5;
    const int gid = lane >> 2, tig = lane & 3;
    const int bh = blockIdx.y, b = bh >> 3, h = bh & 7;
    const int t0 = blockIdx.x * 128;
    const int pbase0 = T_ - 1 - t0 - 127;   // >= 0

    // ---- phase 0: qu/qv hi-lo staging (scaled by 1/sqrt(DK)=0.125) ----
    for (int x = tid; x < 2048; x += 256) {
        int r = x >> 4, c = (x & 15) << 2;
        float4 q4 = *(const float4*)(g_Q + ((size_t)(b * T_ + t0 + r)) * F_ + h * DK_ + c);
        float4 u4 = *(const float4*)(pu + h * DK_ + c);
        float4 v4 = *(const float4*)(pv + h * DK_ + c);
        float qs[4] = {q4.x, q4.y, q4.z, q4.w};
        float us[4] = {u4.x, u4.y, u4.z, u4.w};
        float vs[4] = {v4.x, v4.y, v4.z, v4.w};
#pragma unroll
        for (int e = 0; e < 4; e++) {
            __nv_bfloat16 hh, ll;
            split_hl((qs[e] + us[e]) * 0.125f, hh, ll);
            QUH[r * 72 + c + e] = hh; QUL[r * 72 + c + e] = ll;
            split_hl((qs[e] + vs[e]) * 0.125f, hh, ll);
            QVH[r * 72 + c + e] = hh; QVL[r * 72 + c + e] = ll;
        }
    }
    __syncthreads();

    unsigned quh[4][4], qul[4][4], qvh[4][4], qvl[4][4];
    {
        int ar = warp * 16 + (lane & 15);
        int ac = (lane >> 4) << 3;
#pragma unroll
        for (int kc = 0; kc < 4; kc++) {
            ldsm_x4(smem_u32(&QUH[ar * 72 + kc * 16 + ac]), quh[kc][0], quh[kc][1], quh[kc][2], quh[kc][3]);
            ldsm_x4(smem_u32(&QUL[ar * 72 + kc * 16 + ac]), qul[kc][0], qul[kc][1], qul[kc][2], qul[kc][3]);
            ldsm_x4(smem_u32(&QVH[ar * 72 + kc * 16 + ac]), qvh[kc][0], qvh[kc][1], qvh[kc][2], qvh[kc][3]);
            ldsm_x4(smem_u32(&QVL[ar * 72 + kc * 16 + ac]), qvl[kc][0], qvl[kc][1], qvl[kc][2], qvl[kc][3]);
        }
    }
    __syncthreads();   // P region free from here on

    // ---- initial prefetch: tile 0 K/V (buf 0) + P rows [0,192) ----
    for (int x = tid; x < 512; x += 256) {
        int r = x >> 3, c = (x & 7) << 3;
        size_t ksrc = ((size_t)(b * T_ + r)) * F_ + h * DK_ + c;
        cp16(&KH[r * 72 + c], g_Kh + ksrc);
        cp16(&KL[r * 72 + c], g_Kl + ksrc);
        size_t vsrc = ((size_t)bh * DK_ + r) * T_ + c;
        cp16(&VH[r * 72 + c], g_Vth + vsrc);
        cp16(&VL[r * 72 + c], g_Vtl + vsrc);
    }
    for (int x = tid; x < 1536; x += 256) {
        int rr = x >> 3, c = (x & 7) << 3;
        int grow = pbase0 + rr; if (grow > P_) grow = P_;
        size_t psrc = (size_t)grow * F_ + h * DK_ + c;
        cp16(&PH[rr * 72 + c], g_Ph + psrc);
        cp16(&PL[rr * 72 + c], g_Pl + psrc);
    }
    asm volatile("cp.async.commit_group;");

    float o[8][4];
#pragma unroll
    for (int nt = 0; nt < 8; nt++)
#pragma unroll
        for (int q = 0; q < 4; q++) o[nt][q] = 0.f;
    float mr0 = -1e30f, mr1 = -1e30f, l0 = 0.f, l1 = 0.f;
    float* GSw = GS + warp * (16 * 88);

    for (int i = 0; i < 16; i++) {
        const int s0 = i * 64;

        // ---- prefetch tile i+1 ----
        if (i < 15) {
            __nv_bfloat16* kh = KH + ((i + 1) & 1) * 4608;
            __nv_bfloat16* kl = KL + ((i + 1) & 1) * 4608;
            __nv_bfloat16* vh = VH + ((i + 1) & 1) * 4608;
            __nv_bfloat16* vl = VL + ((i + 1) & 1) * 4608;
            int s0n = s0 + 64;
            for (int x = tid; x < 512; x += 256) {
                int r = x >> 3, c = (x & 7) << 3;
                size_t ksrc = ((size_t)(b * T_ + s0n + r)) * F_ + h * DK_ + c;
                cp16(&kh[r * 72 + c], g_Kh + ksrc);
                cp16(&kl[r * 72 + c], g_Kl + ksrc);
                size_t vsrc = ((size_t)bh * DK_ + r) * T_ + s0n + c;
                cp16(&vh[r * 72 + c], g_Vth + vsrc);
                cp16(&vl[r * 72 + c], g_Vtl + vsrc);
            }
            int u0 = 192 + 64 * i;
            for (int x = tid; x < 512; x += 256) {
                int rr = x >> 3, c = (x & 7) << 3;
                int un = u0 + rr;
                int slot = un & 255;
                int grow = pbase0 + un; if (grow > P_) grow = P_;
                size_t psrc = (size_t)grow * F_ + h * DK_ + c;
                cp16(&PH[slot * 72 + c], g_Ph + psrc);
                cp16(&PL[slot * 72 + c], g_Pl + psrc);
            }
            asm volatile("cp.async.commit_group;");
        }
        if (tid < 64) MSK[tid] = (mask[b * T_ + s0 + tid] == 0) ? -3.0e38f : 0.f;
        if (i < 15) asm volatile("cp.async.wait_group 1;" ::: "memory");
        else        asm volatile("cp.async.wait_group 0;" ::: "memory");
        __syncthreads();

        const __nv_bfloat16* kh = KH + (i & 1) * 4608;
        const __nv_bfloat16* kl = KL + (i & 1) * 4608;
        const __nv_bfloat16* vh = VH + (i & 1) * 4608;
        const __nv_bfloat16* vl = VL + (i & 1) * 4608;
        const int off = (64 * i) & 255;

        // ---- G = qv_strip @ Pwin^T (banded BD, 80 cols per 16-strip) ----
        {
            int prow = 112 - 16 * warp + (lane & 7);
            int psel = ((lane >> 3) & 1) << 3;
#pragma unroll
            for (int nt = 0; nt < 10; nt++) {
                float g0 = 0.f, g1 = 0.f, g2 = 0.f, g3 = 0.f;
                int prw = (prow + nt * 8 + off) & 255;
#pragma unroll
                for (int kc = 0; kc < 4; kc++) {
                    unsigned p0, p1, q0, q1;
                    ldsm_x2(smem_u32(&PH[prw * 72 + kc * 16 + psel]), p0, p1);
                    ldsm_x2(smem_u32(&PL[prw * 72 + kc * 16 + psel]), q0, q1);
                    mma_bf16(g0, g1, g2, g3, qvh[kc][0], qvh[kc][1], qvh[kc][2], qvh[kc][3], p0, p1);
                    mma_bf16(g0, g1, g2, g3, qvh[kc][0], qvh[kc][1], qvh[kc][2], qvh[kc][3], q0, q1);
                    mma_bf16(g0, g1, g2, g3, qvl[kc][0], qvl[kc][1], qvl[kc][2], qvl[kc][3], p0, p1);
                }
                int gc = nt * 8 + 2 * tig;
                GSw[gid * 88 + gc] = g0;
                GSw[gid * 88 + gc + 1] = g1;
                GSw[(gid + 8) * 88 + gc] = g2;
                GSw[(gid + 8) * 88 + gc + 1] = g3;
            }
        }
        __syncwarp();

        // ---- S = qu @ K^T + band(G) + mask ----
        float sf[8][4];
        {
            int krow = lane & 7;
            int ksel = ((lane >> 3) & 1) << 3;
#pragma unroll
            for (int nt = 0; nt < 8; nt++) {
                float a0 = 0.f, a1 = 0.f, a2 = 0.f, a3 = 0.f;
#pragma unroll
                for (int kc = 0; kc < 4; kc++) {
                    unsigned k0, k1, k2, k3;
                    ldsm_x2(smem_u32(&kh[(nt * 8 + krow) * 72 + kc * 16 + ksel]), k0, k1);
                    ldsm_x2(smem_u32(&kl[(nt * 8 + krow) * 72 + kc * 16 + ksel]), k2, k3);
                    mma_bf16(a0, a1, a2, a3, quh[kc][0], quh[kc][1], quh[kc][2], quh[kc][3], k0, k1);
                    mma_bf16(a0, a1, a2, a3, quh[kc][0], quh[kc][1], quh[kc][2], quh[kc][3], k2, k3);
                    mma_bf16(a0, a1, a2, a3, qul[kc][0], qul[kc][1], qul[kc][2], qul[kc][3], k0, k1);
                }
                int col = nt * 8 + 2 * tig;
                sf[nt][0] = a0 + GSw[gid * 88 + col - gid + 15] + MSK[col];
                sf[nt][1] = a1 + GSw[gid * 88 + col - gid + 16] + MSK[col + 1];
                sf[nt][2] = a2 + GSw[(gid + 8) * 88 + col - gid + 7] + MSK[col];
                sf[nt][3] = a3 + GSw[(gid + 8) * 88 + col - gid + 8] + MSK[col + 1];
            }
        }

        // ---- online softmax ----
        float mx0 = -1e30f, mx1 = -1e30f;
#pragma unroll
        for (int nt = 0; nt < 8; nt++) {
            mx0 = fmaxf(mx0, fmaxf(sf[nt][0], sf[nt][1]));
            mx1 = fmaxf(mx1, fmaxf(sf[nt][2], sf[nt][3]));
        }
        mx0 = fmaxf(mx0, __shfl_xor_sync(0xffffffffu, mx0, 1));
        mx0 = fmaxf(mx0, __shfl_xor_sync(0xffffffffu, mx0, 2));
        mx1 = fmaxf(mx1, __shfl_xor_sync(0xffffffffu, mx1, 1));
        mx1 = fmaxf(mx1, __shfl_xor_sync(0xffffffffu, mx1, 2));
        float mn0 = fmaxf(mr0, mx0), mn1 = fmaxf(mr1, mx1);
        float sc0 = __expf(mr0 - mn0), sc1 = __expf(mr1 - mn1);
        float su0 = 0.f, su1 = 0.f;
#pragma unroll
        for (int nt = 0; nt < 8; nt++) {
            sf[nt][0] = __expf(sf[nt][0] - mn0);
            sf[nt][1] = __expf(sf[nt][1] - mn0);
            sf[nt][2] = __expf(sf[nt][2] - mn1);
            sf[nt][3] = __expf(sf[nt][3] - mn1);
            su0 += sf[nt][0] + sf[nt][1];
            su1 += sf[nt][2] + sf[nt][3];
        }
        su0 += __shfl_xor_sync(0xffffffffu, su0, 1);
        su0 += __shfl_xor_sync(0xffffffffu, su0, 2);
        su1 += __shfl_xor_sync(0xffffffffu, su1, 1);
        su1 += __shfl_xor_sync(0xffffffffu, su1, 2);
        l0 = l0 * sc0 + su0;
        l1 = l1 * sc1 + su1;
        mr0 = mn0; mr1 = mn1;
#pragma unroll
        for (int nt = 0; nt < 8; nt++) {
            o[nt][0] *= sc0; o[nt][1] *= sc0;
            o[nt][2] *= sc1; o[nt][3] *= sc1;
        }

        // ---- O += P @ V ----
        {
            int vrow = lane & 7;
            int vsel = ((lane >> 3) & 1) << 3;
#pragma unroll
            for (int kc = 0; kc < 4; kc++) {
                unsigned ah[4], al[4];
                pack_hl(sf[2 * kc][0], sf[2 * kc][1], ah[0], al[0]);
                pack_hl(sf[2 * kc][2], sf[2 * kc][3], ah[1], al[1]);
                pack_hl(sf[2 * kc + 1][0], sf[2 * kc + 1][1], ah[2], al[2]);
                pack_hl(sf[2 * kc + 1][2], sf[2 * kc + 1][3], ah[3], al[3]);
#pragma unroll
                for (int nt = 0; nt < 8; nt++) {
                    unsigned v0, v1, w0, w1;
                    ldsm_x2(smem_u32(&vh[(nt * 8 + vrow) * 72 + kc * 16 + vsel]), v0, v1);
                    ldsm_x2(smem_u32(&vl[(nt * 8 + vrow) * 72 + kc * 16 + vsel]), w0, w1);
                    mma_bf16(o[nt][0], o[nt][1], o[nt][2], o[nt][3],
                             ah[0], ah[1], ah[2], ah[3], v0, v1);
                    mma_bf16(o[nt][0], o[nt][1], o[nt][2], o[nt][3],
                             ah[0], ah[1], ah[2], ah[3], w0, w1);
                    mma_bf16(o[nt][0], o[nt][1], o[nt][2], o[nt][3],
                             al[0], al[1], al[2], al[3], v0, v1);
                }
            }
        }
        __syncthreads();
    }

    // ---- epilogue ----
    float inv0 = (l0 > 0.f) ? 1.f / l0 : 0.f;
    float inv1 = (l1 > 0.f) ? 1.f / l1 : 0.f;
    int row0 = t0 + warp * 16 + gid;
#pragma unroll
    for (int nt = 0; nt < 8; nt++) {
        int colg = h * DK_ + nt * 8 + 2 * tig;
        float2 w0 = make_float2(o[nt][0] * inv0, o[nt][1] * inv0);
        *(float2*)&g_ctx[((size_t)(b * T_ + row0)) * F_ + colg] = w0;
        float2 w1 = make_float2(o[nt][2] * inv1, o[nt][3] * inv1);
        *(float2*)&g_ctx[((size_t)(b * T_ + row0 + 8)) * F_ + colg] = w1;
    }
}

// =====================================================================
extern "C" void kernel_launch(void* const* d_in, const int* in_sizes, int n_in,
                              void* d_out, int out_size)
{
    const float* query   = (const float*)d_in[0];
    const float* key_in  = (const float*)d_in[1];
    const float* value   = (const float*)d_in[2];
    const float* pos_emb = (const float*)d_in[3];
    const int*   mask    = (const int*)d_in[4];
    const float* Wq = (const float*)d_in[5];
    const float* bq = (const float*)d_in[6];
    const float* Wk = (const float*)d_in[7];
    const float* bk = (const float*)d_in[8];
    const float* Wv = (const float*)d_in[9];
    const float* bv = (const float*)d_in[10];
    const float* Wo = (const float*)d_in[11];
    const float* bo = (const float*)d_in[12];
    const float* Wp = (const float*)d_in[13];
    const float* pu = (const float*)d_in[14];
    const float* pv = (const float*)d_in[15];
    float* out = (float*)d_out;

    float *Qp, *Cp;
    __nv_bfloat16 *Khp, *Klp, *Vthp, *Vtlp, *Php, *Plp;
    cudaGetSymbolAddress((void**)&Qp,   g_Q);
    cudaGetSymbolAddress((void**)&Cp,   g_ctx);
    cudaGetSymbolAddress((void**)&Khp,  g_Kh);
    cudaGetSymbolAddress((void**)&Klp,  g_Kl);
    cudaGetSymbolAddress((void**)&Vthp, g_Vth);
    cudaGetSymbolAddress((void**)&Vtlp, g_Vtl);
    cudaGetSymbolAddress((void**)&Php,  g_Ph);
    cudaGetSymbolAddress((void**)&Plp,  g_Pl);

    cudaFuncSetAttribute(flash_kernel, cudaFuncAttributeMaxDynamicSharedMemorySize, FL_SMEM);

    // ---- all 4 input projections in ONE launch (grid.z = job id) ----
    GemmJobs pj;
    pj.j[0] = { query,   Wq, bq,      Qp,      nullptr, nullptr, B_ * T_, 0 };
    pj.j[1] = { key_in,  Wk, bk,      nullptr, Khp,     Klp,     B_ * T_, 1 };
    pj.j[2] = { value,   Wv, bv,      nullptr, Vthp,    Vtlp,    B_ * T_, 2 };
    pj.j[3] = { pos_emb, Wp, nullptr, nullptr, Php,     Plp,     P_,      1 };
    gemm_multi<<<dim3(4, 64, 4), 256>>>(pj);

    // fused attention (scores + rel-shift + softmax + AV), pipelined
    flash_kernel<<<dim3(8, B_ * H_), 256, FL_SMEM>>>(pu, pv, mask);

    // output projection
    GemmJobs oj;
    oj.j[0] = { Cp, Wo, bo, out, nullptr, nullptr, B_ * T_, 0 };
    oj.j[1] = oj.j[0]; oj.j[2] = oj.j[0]; oj.j[3] = oj.j[0];
    gemm_multi<<<dim3(4, 64, 1), 256>>>(oj);
}